// round 7
// baseline (speedup 1.0000x reference)
#include <cuda_runtime.h>
#include <cuda_fp16.h>
#include <math.h>

#define NB 128    // batch
#define TT 2000   // attention time steps
#define LL 250    // decode length
#define HH 512    // hidden
#define KK 128    // key size
#define VV 128    // value size
#define AA 64     // alphabet
#define NBLK 256
#define NTHR 256

// ---------------- device scratch ----------------
__device__ __half g_kb[(size_t)TT * NB * KK];          // fp16 keys   (65.5 MB)
__device__ __half g_vb[(size_t)TT * NB * VV];          // fp16 values (65.5 MB)
__device__ float g_PbT[2048 * 64];                     // transposed token gate-base
__device__ float g_h1T[2 * HH * NB], g_c1T[HH * NB];   // feature-major state
__device__ float g_h2T[2 * KK * NB], g_c2T[KK * NB];
__device__ float g_ctxT[VV * NB];
__device__ float g_pm[NB * NBLK], g_ps[NB * NBLK];
__device__ float g_pacc[(size_t)NB * NBLK * VV];       // 16.8 MB
__device__ int   g_acnt[NB];
__device__ int   g_prefix[NB + 1];
__device__ int   g_bfirst[NB], g_blast[NB], g_bcnt[NB];
__device__ unsigned g_gen, g_cnt;

__device__ __forceinline__ float sigf(float x) { return 1.0f / (1.0f + __expf(-x)); }

__device__ __forceinline__ void gbar() {
    __syncthreads();
    __threadfence();
    if (threadIdx.x == 0) {
        unsigned my = *(volatile unsigned*)&g_gen;
        unsigned old = atomicAdd(&g_cnt, 1u);
        if (old == NBLK - 1) {
            g_cnt = 0u;
            __threadfence();
            atomicAdd(&g_gen, 1u);
        } else {
            while (*(volatile unsigned*)&g_gen == my) { __nanosleep(64); }
        }
        __threadfence();
    }
    __syncthreads();
}

// ---------------- init ----------------
__global__ void init_kernel(const float* __restrict__ values) {
    int i = blockIdx.x * 256 + threadIdx.x;          // 65536 threads
    if (i < HH * NB) { g_h1T[i] = 0.0f; g_c1T[i] = 0.0f;
                       g_h1T[HH * NB + i] = 0.0f; }
    if (i < KK * NB) {
        g_h2T[i] = 0.0f; g_c2T[i] = 0.0f; g_h2T[KK * NB + i] = 0.0f;
        int v = i >> 7, n = i & 127;
        g_ctxT[v * NB + n] = values[n * VV + v];      // ctx0 = values[0]
    }
    if (i < NB) g_acnt[i] = 0;
}

// ---------------- meta: prefix sums + per-n block coverage ----------------
__global__ void meta_kernel(const int* __restrict__ lens) {
    __shared__ int pre[NB + 1];
    if (threadIdx.x == 0) {
        int s = 0;
        for (int n = 0; n < NB; n++) { pre[n] = s; s += lens[n]; }
        pre[NB] = s;
        for (int i = 0; i <= NB; i++) g_prefix[i] = pre[i];
    }
    __syncthreads();
    int n = threadIdx.x;
    if (n < NB) {
        long long W = pre[NB];
        int Pn = pre[n], Pn1 = pre[n + 1];
        int bf = 0, bl = 0, cnt = 0;
        for (int b = 0; b < NBLK; b++) {
            int r0 = (int)((long long)b * W / NBLK);
            int r1 = (int)((long long)(b + 1) * W / NBLK);
            int lo = max(r0, Pn), hi = min(r1, Pn1);
            if (lo < hi) { if (cnt == 0) bf = b; bl = b; cnt++; }
        }
        g_bfirst[n] = bf; g_blast[n] = bl; g_bcnt[n] = cnt;
    }
}

// ---------------- fp16 conversion ----------------
__global__ void conv_kernel(const float* __restrict__ key, const float* __restrict__ val) {
    size_t stride = (size_t)gridDim.x * blockDim.x;
    for (size_t i = (size_t)blockIdx.x * blockDim.x + threadIdx.x;
         i < (size_t)TT * NB * KK; i += stride) {
        g_kb[i] = __float2half(key[i]);
        g_vb[i] = __float2half(val[i]);
    }
}

// ------------- PbT[ca][tok] = (emb @ W_ih1[:, :512]^T + b_ih1 + b_hh1)^T ----
__global__ __launch_bounds__(256) void pb_kernel(
    const float* __restrict__ emb, const float* __restrict__ W_ih1,
    const float* __restrict__ b_ih1, const float* __restrict__ b_hh1)
{
    const int c0 = blockIdx.x * 32;                  // 64 blocks
    const int col = threadIdx.x & 31, rg = threadIdx.x >> 5;
    const int ca = c0 + col;
    float acc[8];
#pragma unroll
    for (int i = 0; i < 8; i++) acc[i] = 0.0f;
    for (int k = 0; k < HH; k++) {
        float w = W_ih1[(size_t)ca * 640 + k];
#pragma unroll
        for (int i = 0; i < 8; i++)
            acc[i] = fmaf(emb[(size_t)(rg * 8 + i) * HH + k], w, acc[i]);
    }
    float bb = b_ih1[ca] + b_hh1[ca];
#pragma unroll
    for (int i = 0; i < 8; i++)
        g_PbT[(size_t)ca * 64 + rg * 8 + i] = acc[i] + bb;
}

// ---------------- persistent main kernel ----------------
struct SA {                    // phase A scratch (vector-read arrays 16B-aligned)
    float Xs[16][64];
    float Ws[16][17];
    float sg[16][68];
    int toks[64];
};
struct SB {                    // phase B scratch
    float Xs[16][128];
    float sg[4][132];
};
struct SC {                    // phase C scratch — float4-accessed arrays FIRST
    float h2s[KK];             // offset 0
    float wacc[8][VV];         // offset 512 (16B-aligned)
    float ctxs[VV];
    float wm[8], wsum[8];
    int   prefix[NB + 1];      // scalar-only access; keep after vector arrays
    int   flag;
};

__global__ __launch_bounds__(NTHR, 2) void decoder_main(
    const int* __restrict__ text,
    const float* __restrict__ W_ih1, const float* __restrict__ W_hh1,
    const float* __restrict__ W_ih2, const float* __restrict__ W_hh2,
    const float* __restrict__ b_ih2, const float* __restrict__ b_hh2,
    const float* __restrict__ W_mos, const float* __restrict__ b_mos,
    float* __restrict__ out)
{
    __shared__ float WsB[4][644];
    __shared__ __align__(16) union { SA a; SB b; SC c; } scr;

    const int blk = blockIdx.x;
    const int tid = threadIdx.x;

    // one-time LSTM2 weight preload (blocks < 128)
    if (blk < 128) {
#pragma unroll 1
        for (int it = 0; it < 10; it++) {
            int idx = it * 256 + tid;                // 4*640
            int c = idx / 640, k = idx - c * 640;
            int ca = c * 128 + blk;
            WsB[c][k] = (k < HH) ? W_ih2[(size_t)ca * HH + k]
                                 : W_hh2[(size_t)ca * KK + (k - HH)];
        }
    }
    __syncthreads();

    for (int l = 0; l < LL; l++) {
        const int p = l & 1;

        // ===== phase A: LSTM1 gates (16 cols x 64 n per block) + apply =====
        {
            SA& sa = scr.a;
            const int ct = blk >> 1, nh = blk & 1, u0 = ct * 4;
            if (tid < 64) sa.toks[tid] = text[(nh * 64 + tid) * LL + l];
            const int col = tid & 15, ng = tid >> 4;
            const int caC = ((col & 3) << 9) + u0 + (col >> 2);
            const int kW = tid & 15, cW = tid >> 4;
            const int caW = ((cW & 3) << 9) + u0 + (cW >> 2);
            const int nn = tid & 63, kofs = tid >> 6;
            const int gn = nh * 64 + nn;
            const float* h1r = g_h1T + (size_t)p * (HH * NB);
            __syncthreads();

            float acc0 = g_PbT[(size_t)caC * 64 + sa.toks[(ng << 2) + 0]];
            float acc1 = g_PbT[(size_t)caC * 64 + sa.toks[(ng << 2) + 1]];
            float acc2 = g_PbT[(size_t)caC * 64 + sa.toks[(ng << 2) + 2]];
            float acc3 = g_PbT[(size_t)caC * 64 + sa.toks[(ng << 2) + 3]];

            float xr[4], wr;
#pragma unroll
            for (int it = 0; it < 4; it++) {
                int kg = kofs + (it << 2);
                xr[it] = (kg < VV) ? __ldcg(&g_ctxT[kg * NB + gn])
                                   : __ldcg(&h1r[(kg - VV) * NB + gn]);
            }
            wr = (kW < VV) ? W_ih1[(size_t)caW * 640 + 512 + kW]
                           : W_hh1[(size_t)caW * 512 + (kW - VV)];

#pragma unroll 1
            for (int ch = 0; ch < 40; ch++) {
                __syncthreads();
#pragma unroll
                for (int it = 0; it < 4; it++) sa.Xs[(it << 2) + kofs][nn] = xr[it];
                sa.Ws[kW][cW] = wr;
                __syncthreads();
                if (ch < 39) {
                    const int kb2 = (ch + 1) << 4;
#pragma unroll
                    for (int it = 0; it < 4; it++) {
                        int kg = kb2 + kofs + (it << 2);
                        xr[it] = (kg < VV) ? __ldcg(&g_ctxT[kg * NB + gn])
                                           : __ldcg(&h1r[(kg - VV) * NB + gn]);
                    }
                    int kg = kb2 + kW;
                    wr = (kg < VV) ? W_ih1[(size_t)caW * 640 + 512 + kg]
                                   : W_hh1[(size_t)caW * 512 + (kg - VV)];
                }
#pragma unroll
                for (int k = 0; k < 16; k++) {
                    float w = sa.Ws[k][col];
                    float4 x = *(const float4*)&sa.Xs[k][ng << 2];
                    acc0 = fmaf(x.x, w, acc0);
                    acc1 = fmaf(x.y, w, acc1);
                    acc2 = fmaf(x.z, w, acc2);
                    acc3 = fmaf(x.w, w, acc3);
                }
            }
            __syncthreads();
            sa.sg[col][(ng << 2) + 0] = acc0;
            sa.sg[col][(ng << 2) + 1] = acc1;
            sa.sg[col][(ng << 2) + 2] = acc2;
            sa.sg[col][(ng << 2) + 3] = acc3;
            __syncthreads();
            const int u = tid >> 6, an = tid & 63;
            float gi = sa.sg[4 * u + 0][an];
            float gf = sa.sg[4 * u + 1][an];
            float gg = sa.sg[4 * u + 2][an];
            float go = sa.sg[4 * u + 3][an];
            int ci = (u0 + u) * NB + nh * 64 + an;
            float cn = sigf(gf) * g_c1T[ci] + sigf(gi) * tanhf(gg);
            g_c1T[ci] = cn;
            g_h1T[(size_t)(p ^ 1) * (HH * NB) + ci] = sigf(go) * tanhf(cn);
        }
        gbar();

        // ===== phase B: LSTM2 gates (4 cols x 128 n, blocks < 128) + apply =====
        if (blk < 128) {
            SB& sb = scr.b;
            const int col = tid & 3, ng = tid >> 2;
            const int nn = tid & 127, kofs = tid >> 7;
            const float* h1r = g_h1T + (size_t)(p ^ 1) * (HH * NB);
            const float* h2r = g_h2T + (size_t)p * (KK * NB);
            float acc0 = 0.0f, acc1 = 0.0f;

            float xr[8];
#pragma unroll
            for (int it = 0; it < 8; it++) {
                int kg = kofs + (it << 1);
                xr[it] = (kg < HH) ? __ldcg(&h1r[kg * NB + nn])
                                   : __ldcg(&h2r[(kg - HH) * NB + nn]);
            }
#pragma unroll 1
            for (int ch = 0; ch < 40; ch++) {
                __syncthreads();
#pragma unroll
                for (int it = 0; it < 8; it++) sb.Xs[(it << 1) + kofs][nn] = xr[it];
                __syncthreads();
                if (ch < 39) {
                    const int kb2 = (ch + 1) << 4;
#pragma unroll
                    for (int it = 0; it < 8; it++) {
                        int kg = kb2 + kofs + (it << 1);
                        xr[it] = (kg < HH) ? __ldcg(&h1r[kg * NB + nn])
                                           : __ldcg(&h2r[(kg - HH) * NB + nn]);
                    }
                }
                const int kb = ch << 4;
#pragma unroll
                for (int k = 0; k < 16; k++) {
                    float w = WsB[col][kb + k];
                    float2 x = *(const float2*)&sb.Xs[k][ng << 1];
                    acc0 = fmaf(x.x, w, acc0);
                    acc1 = fmaf(x.y, w, acc1);
                }
            }
            __syncthreads();
            sb.sg[col][(ng << 1) + 0] = acc0;
            sb.sg[col][(ng << 1) + 1] = acc1;
            __syncthreads();
            if (tid < 128) {
                const int nn2 = tid;
                float gi = sb.sg[0][nn2] + b_ih2[blk]       + b_hh2[blk];
                float gf = sb.sg[1][nn2] + b_ih2[128 + blk] + b_hh2[128 + blk];
                float gg = sb.sg[2][nn2] + b_ih2[256 + blk] + b_hh2[256 + blk];
                float go = sb.sg[3][nn2] + b_ih2[384 + blk] + b_hh2[384 + blk];
                int ci = blk * NB + nn2;
                float cn = sigf(gf) * g_c2T[ci] + sigf(gi) * tanhf(gg);
                g_c2T[ci] = cn;
                g_h2T[(size_t)(p ^ 1) * (KK * NB) + ci] = sigf(go) * tanhf(cn);
            }
        }
        gbar();

        // ===== phase C: balanced flash attention + combine + MoS =====
        {
            SC& sc = scr.c;
            if (tid <= NB) sc.prefix[tid] = g_prefix[tid];
            __syncthreads();
            const long long W = sc.prefix[NB];
            const int r0 = (int)((long long)blk * W / NBLK);
            const int r1 = (int)((long long)(blk + 1) * W / NBLK);
            const int warp = tid >> 5, lane = tid & 31;

            int n0 = 0;
            for (int n = 1; n < NB; n++) { if (sc.prefix[n] <= r0) n0 = n; else break; }

            for (int n = n0; n < NB && sc.prefix[n] < r1; n++) {
                const int Pn = sc.prefix[n], Pn1 = sc.prefix[n + 1];
                const int tlo = max(r0, Pn) - Pn;
                const int thi = min(r1, Pn1) - Pn;
                if (thi <= tlo) continue;

                if (tid < KK)
                    sc.h2s[tid] = __ldcg(&g_h2T[(size_t)(p ^ 1) * (KK * NB) + tid * NB + n]);
                __syncthreads();
                const float4 hv = *(const float4*)&sc.h2s[lane << 2];

                float m = -1e30f, ssum = 0.0f;
                float4 acc = make_float4(0.f, 0.f, 0.f, 0.f);
                const size_t rowstride = (size_t)NB * KK;
                const size_t base = (size_t)n * KK + (lane << 2);

                int t = tlo + warp;
                for (; t + 24 < thi; t += 32) {
                    const __half* kp = g_kb + (size_t)t * rowstride + base;
                    const __half* vp = g_vb + (size_t)t * rowstride + base;
                    uint2 kw0 = *(const uint2*)kp;
                    uint2 kw1 = *(const uint2*)(kp + 8 * rowstride);
                    uint2 kw2 = *(const uint2*)(kp + 16 * rowstride);
                    uint2 kw3 = *(const uint2*)(kp + 24 * rowstride);
                    uint2 vw0 = *(const uint2*)vp;
                    uint2 vw1 = *(const uint2*)(vp + 8 * rowstride);
                    uint2 vw2 = *(const uint2*)(vp + 16 * rowstride);
                    uint2 vw3 = *(const uint2*)(vp + 24 * rowstride);
                    float2 a0 = __half22float2(*(__half2*)&kw0.x);
                    float2 b0 = __half22float2(*(__half2*)&kw0.y);
                    float2 a1 = __half22float2(*(__half2*)&kw1.x);
                    float2 b1 = __half22float2(*(__half2*)&kw1.y);
                    float2 a2 = __half22float2(*(__half2*)&kw2.x);
                    float2 b2 = __half22float2(*(__half2*)&kw2.y);
                    float2 a3 = __half22float2(*(__half2*)&kw3.x);
                    float2 b3 = __half22float2(*(__half2*)&kw3.y);
                    float d0 = a0.x * hv.x + a0.y * hv.y + b0.x * hv.z + b0.y * hv.w;
                    float d1 = a1.x * hv.x + a1.y * hv.y + b1.x * hv.z + b1.y * hv.w;
                    float d2 = a2.x * hv.x + a2.y * hv.y + b2.x * hv.z + b2.y * hv.w;
                    float d3 = a3.x * hv.x + a3.y * hv.y + b3.x * hv.z + b3.y * hv.w;
#pragma unroll
                    for (int o = 16; o; o >>= 1) {
                        d0 += __shfl_xor_sync(0xffffffffu, d0, o);
                        d1 += __shfl_xor_sync(0xffffffffu, d1, o);
                        d2 += __shfl_xor_sync(0xffffffffu, d2, o);
                        d3 += __shfl_xor_sync(0xffffffffu, d3, o);
                    }
                    float mx = fmaxf(fmaxf(d0, d1), fmaxf(d2, d3));
                    float mn = fmaxf(m, mx);
                    float scale = __expf(m - mn);
                    float p0 = __expf(d0 - mn), p1 = __expf(d1 - mn);
                    float p2 = __expf(d2 - mn), p3 = __expf(d3 - mn);
                    ssum = ssum * scale + ((p0 + p1) + (p2 + p3));
                    float2 va0 = __half22float2(*(__half2*)&vw0.x);
                    float2 vb0 = __half22float2(*(__half2*)&vw0.y);
                    float2 va1 = __half22float2(*(__half2*)&vw1.x);
                    float2 vb1 = __half22float2(*(__half2*)&vw1.y);
                    float2 va2 = __half22float2(*(__half2*)&vw2.x);
                    float2 vb2 = __half22float2(*(__half2*)&vw2.y);
                    float2 va3 = __half22float2(*(__half2*)&vw3.x);
                    float2 vb3 = __half22float2(*(__half2*)&vw3.y);
                    acc.x = acc.x * scale + p0 * va0.x + p1 * va1.x + p2 * va2.x + p3 * va3.x;
                    acc.y = acc.y * scale + p0 * va0.y + p1 * va1.y + p2 * va2.y + p3 * va3.y;
                    acc.z = acc.z * scale + p0 * vb0.x + p1 * vb1.x + p2 * vb2.x + p3 * vb3.x;
                    acc.w = acc.w * scale + p0 * vb0.y + p1 * vb1.y + p2 * vb2.y + p3 * vb3.y;
                    m = mn;
                }
                for (; t < thi; t += 8) {
                    const __half* kp = g_kb + (size_t)t * rowstride + base;
                    const __half* vp = g_vb + (size_t)t * rowstride + base;
                    uint2 kw = *(const uint2*)kp;
                    uint2 vw = *(const uint2*)vp;
                    float2 a0 = __half22float2(*(__half2*)&kw.x);
                    float2 b0 = __half22float2(*(__half2*)&kw.y);
                    float d = a0.x * hv.x + a0.y * hv.y + b0.x * hv.z + b0.y * hv.w;
#pragma unroll
                    for (int o = 16; o; o >>= 1) d += __shfl_xor_sync(0xffffffffu, d, o);
                    float mn = fmaxf(m, d);
                    float scale = __expf(m - mn);
                    float pp = __expf(d - mn);
                    ssum = ssum * scale + pp;
                    float2 va = __half22float2(*(__half2*)&vw.x);
                    float2 vb = __half22float2(*(__half2*)&vw.y);
                    acc.x = acc.x * scale + pp * va.x;
                    acc.y = acc.y * scale + pp * va.y;
                    acc.z = acc.z * scale + pp * vb.x;
                    acc.w = acc.w * scale + pp * vb.y;
                    m = mn;
                }

                if (lane == 0) { sc.wm[warp] = m; sc.wsum[warp] = ssum; }
                *(float4*)&sc.wacc[warp][lane << 2] = acc;
                __syncthreads();

                const int slot = blk - g_bfirst[n];
                if (tid < VV) {
                    float mm = -1e30f;
#pragma unroll
                    for (int w = 0; w < 8; w++) mm = fmaxf(mm, sc.wm[w]);
                    float S = 0.0f, C = 0.0f;
#pragma unroll
                    for (int w = 0; w < 8; w++) {
                        float e = __expf(sc.wm[w] - mm);
                        S += e * sc.wsum[w];
                        C += e * sc.wacc[w][tid];
                    }
                    g_pacc[((size_t)n * NBLK + slot) * VV + tid] = C;
                    if (tid == 0) { g_pm[n * NBLK + slot] = mm; g_ps[n * NBLK + slot] = S; }
                    __threadfence();
                }
                __syncthreads();
                if (tid == 0) {
                    int old = atomicAdd(&g_acnt[n], 1);
                    __threadfence();
                    sc.flag = (old == g_bcnt[n] - 1);
                }
                __syncthreads();
                if (sc.flag) {
                    const int bf = g_bfirst[n], bl = g_blast[n];
                    if (tid < VV) {
                        float mm = -1e30f;
                        for (int bb = bf; bb <= bl; bb++) {
                            int rr0 = (int)((long long)bb * W / NBLK);
                            int rr1 = (int)((long long)(bb + 1) * W / NBLK);
                            if (max(rr0, Pn) < min(rr1, Pn1))
                                mm = fmaxf(mm, __ldcg(&g_pm[n * NBLK + (bb - bf)]));
                        }
                        float S = 0.0f, C = 0.0f;
                        for (int bb = bf; bb <= bl; bb++) {
                            int rr0 = (int)((long long)bb * W / NBLK);
                            int rr1 = (int)((long long)(bb + 1) * W / NBLK);
                            if (max(rr0, Pn) < min(rr1, Pn1)) {
                                int s2 = bb - bf;
                                float e = __expf(__ldcg(&g_pm[n * NBLK + s2]) - mm);
                                S += e * __ldcg(&g_ps[n * NBLK + s2]);
                                C += e * __ldcg(&g_pacc[((size_t)n * NBLK + s2) * VV + tid]);
                            }
                        }
                        float cv = C / S;
                        sc.ctxs[tid] = cv;
                        g_ctxT[tid * NB + n] = cv;
                    }
                    if (tid == 0) g_acnt[n] = 0;
                    __syncthreads();
                    if (tid < AA) {
                        float a = b_mos[tid];
                        const float* w = W_mos + (size_t)tid * (KK + VV);
#pragma unroll 4
                        for (int k = 0; k < KK; k++) a = fmaf(sc.h2s[k], w[k], a);
#pragma unroll 4
                        for (int v = 0; v < VV; v++) a = fmaf(sc.ctxs[v], w[KK + v], a);
                        out[((size_t)n * LL + l) * AA + tid] = a;
                    }
                }
                __syncthreads();
            }
        }
        gbar();
    }
}

// ---------------- launch ----------------
extern "C" void kernel_launch(void* const* d_in, const int* in_sizes, int n_in,
                              void* d_out, int out_size) {
    (void)in_sizes; (void)n_in; (void)out_size;
    const float* key    = (const float*)d_in[0];
    const float* values = (const float*)d_in[1];
    const int*   lens   = (const int*)  d_in[2];
    const int*   text   = (const int*)  d_in[3];
    const float* emb    = (const float*)d_in[4];
    const float* W_ih1  = (const float*)d_in[5];
    const float* W_hh1  = (const float*)d_in[6];
    const float* b_ih1  = (const float*)d_in[7];
    const float* b_hh1  = (const float*)d_in[8];
    const float* W_ih2  = (const float*)d_in[9];
    const float* W_hh2  = (const float*)d_in[10];
    const float* b_ih2  = (const float*)d_in[11];
    const float* b_hh2  = (const float*)d_in[12];
    const float* W_mos  = (const float*)d_in[13];
    const float* b_mos  = (const float*)d_in[14];
    float* out = (float*)d_out;

    init_kernel<<<256, 256>>>(values);
    meta_kernel<<<1, 256>>>(lens);
    conv_kernel<<<4096, 256>>>(key, values);
    pb_kernel<<<64, 256>>>(emb, W_ih1, b_ih1, b_hh1);
    decoder_main<<<NBLK, NTHR>>>(text, W_ih1, W_hh1, W_ih2, W_hh2,
                                 b_ih2, b_hh2, W_mos, b_mos, out);
}

// round 8
// speedup vs baseline: 1.4740x; 1.4740x over previous
#include <cuda_runtime.h>
#include <cuda_fp16.h>
#include <math.h>
#include <stdint.h>

#define NB 128
#define TT 2000
#define LL 250
#define HH 512
#define KK 128
#define VV 128
#define AA 64
#define NBLK 256
#define NTHR 256

__device__ __align__(16) __half g_kb[(size_t)NB * TT * 128];
__device__ __align__(16) __half g_vb[(size_t)NB * TT * 128];
__device__ __align__(16) __half g_W1p[2048 * 640];
__device__ __align__(16) __half g_W2p[512 * 640];
__device__ __align__(16) __half g_x1[2][640 * 128];   // rows: 0-127 ctx, 128-639 h1
__device__ __align__(16) __half g_x2[2][640 * 128];   // rows: 0-511 h1, 512-639 h2
__device__ float g_h2N[128 * 128];                    // h2 fp32 [n][k]
__device__ float g_PbT[2048 * 64];
__device__ float g_c1[512 * 128], g_c2[128 * 128];
__device__ float g_pm[NB * NBLK], g_ps[NB * NBLK];
__device__ float g_pacc[(size_t)NB * NBLK * VV];
__device__ int   g_acnt[NB];
__device__ int   g_prefix[NB + 1];
__device__ int   g_bfirst[NB], g_blast[NB], g_bcnt[NB];
__device__ unsigned g_gen, g_cnt;

struct SCt {
    float h2s[128];
    float wacc[8][128];
    float ctxs[128];
    float wm[8], wsum[8];
    int   prefix[NB + 1];
    int   flag;
};

#define OFF_W1 0
#define OFF_W2 21248
#define OFF_XS 42496
#define OFF_U  59904
#define SMEM_TOTAL 68608
#define WST 664
#define XST 136

__device__ __forceinline__ float sigf(float x) { return 1.0f / (1.0f + __expf(-x)); }
__device__ __forceinline__ uint32_t cvta_s(const void* p) { return (uint32_t)__cvta_generic_to_shared(p); }
__device__ __forceinline__ void ldsm_x4(uint32_t& a0, uint32_t& a1, uint32_t& a2, uint32_t& a3, uint32_t a) {
    asm volatile("ldmatrix.sync.aligned.m8n8.x4.shared.b16 {%0,%1,%2,%3},[%4];"
        : "=r"(a0), "=r"(a1), "=r"(a2), "=r"(a3) : "r"(a));
}
__device__ __forceinline__ void ldsm_x2t(uint32_t& b0, uint32_t& b1, uint32_t a) {
    asm volatile("ldmatrix.sync.aligned.m8n8.x2.trans.shared.b16 {%0,%1},[%2];"
        : "=r"(b0), "=r"(b1) : "r"(a));
}
__device__ __forceinline__ void ldsm_x4t(uint32_t& b0, uint32_t& b1, uint32_t& b2, uint32_t& b3, uint32_t a) {
    asm volatile("ldmatrix.sync.aligned.m8n8.x4.trans.shared.b16 {%0,%1,%2,%3},[%4];"
        : "=r"(b0), "=r"(b1), "=r"(b2), "=r"(b3) : "r"(a));
}
__device__ __forceinline__ void mma16816(float& d0, float& d1, float& d2, float& d3,
    uint32_t a0, uint32_t a1, uint32_t a2, uint32_t a3, uint32_t b0, uint32_t b1) {
    asm volatile("mma.sync.aligned.m16n8k16.row.col.f32.f16.f16.f32 "
        "{%0,%1,%2,%3},{%4,%5,%6,%7},{%8,%9},{%0,%1,%2,%3};"
        : "+f"(d0), "+f"(d1), "+f"(d2), "+f"(d3)
        : "r"(a0), "r"(a1), "r"(a2), "r"(a3), "r"(b0), "r"(b1));
}

__device__ __forceinline__ void gbar() {
    __syncthreads();
    __threadfence();
    if (threadIdx.x == 0) {
        unsigned my = *(volatile unsigned*)&g_gen;
        unsigned old = atomicAdd(&g_cnt, 1u);
        if (old == NBLK - 1) { g_cnt = 0u; __threadfence(); atomicAdd(&g_gen, 1u); }
        else { while (*(volatile unsigned*)&g_gen == my) { __nanosleep(64); } }
        __threadfence();
    }
    __syncthreads();
}

__global__ void init2_kernel(const float* __restrict__ values) {
    int i = blockIdx.x * 256 + threadIdx.x;   // 512 blocks
    if (i < 512 * 128) g_c1[i] = 0.0f;
    if (i < 128 * 128) { g_c2[i] = 0.0f; g_x2[1][512 * 128 + i] = __float2half(0.0f); }
    if (i < 640 * 128) {
        int k = i >> 7, n = i & 127;
        g_x1[0][i] = (k < 128) ? __float2half(values[n * 128 + k]) : __float2half(0.0f);
    }
    if (i < NB) g_acnt[i] = 0;
}

__global__ void meta_kernel(const int* __restrict__ lens) {
    __shared__ int pre[NB + 1];
    if (threadIdx.x == 0) {
        int s = 0;
        for (int n = 0; n < NB; n++) { pre[n] = s; s += lens[n]; }
        pre[NB] = s;
        for (int i = 0; i <= NB; i++) g_prefix[i] = pre[i];
    }
    __syncthreads();
    int n = threadIdx.x;
    if (n < NB) {
        long long W = pre[NB];
        int Pn = pre[n], Pn1 = pre[n + 1], bf = 0, bl = 0, cnt = 0;
        for (int b = 0; b < NBLK; b++) {
            int r0 = (int)((long long)b * W / NBLK);
            int r1 = (int)((long long)(b + 1) * W / NBLK);
            if (max(r0, Pn) < min(r1, Pn1)) { if (cnt == 0) bf = b; bl = b; cnt++; }
        }
        g_bfirst[n] = bf; g_blast[n] = bl; g_bcnt[n] = cnt;
    }
}

__global__ void convkv_kernel(const float* __restrict__ key, const float* __restrict__ val) {
    int rid = blockIdx.x * 8 + (threadIdx.x >> 5);   // 32000 blocks
    int lane = threadIdx.x & 31;
    if (rid < TT * NB) {
        int t = rid >> 7, n = rid & 127;
        float4 kv = *(const float4*)(key + ((size_t)rid << 7) + (lane << 2));
        float4 vv = *(const float4*)(val + ((size_t)rid << 7) + (lane << 2));
        size_t dst = ((size_t)n * TT + t) * 128 + (lane << 2);
        ((__half2*)(g_kb + dst))[0] = __floats2half2_rn(kv.x, kv.y);
        ((__half2*)(g_kb + dst))[1] = __floats2half2_rn(kv.z, kv.w);
        ((__half2*)(g_vb + dst))[0] = __floats2half2_rn(vv.x, vv.y);
        ((__half2*)(g_vb + dst))[1] = __floats2half2_rn(vv.z, vv.w);
    }
}

__global__ void convw_kernel(const float* __restrict__ W_ih1, const float* __restrict__ W_hh1,
                             const float* __restrict__ W_ih2, const float* __restrict__ W_hh2) {
    int idx = blockIdx.x;   // 2560
    if (idx < 2048) {
        int ct = idx >> 4, r = idx & 15;
        int ca = ((r & 3) << 9) + ct * 4 + (r >> 2);
        for (int k = threadIdx.x; k < 640; k += 256) {
            float v = (k < 128) ? W_ih1[(size_t)ca * 640 + 512 + k]
                                : W_hh1[(size_t)ca * 512 + (k - 128)];
            g_W1p[(size_t)idx * 640 + k] = __float2half(v);
        }
    } else {
        int i2 = idx - 2048, ct = i2 >> 4, r = i2 & 15;
        int cb = ((r & 3) << 7) + ct * 4 + (r >> 2);
        for (int k = threadIdx.x; k < 640; k += 256) {
            float v = (k < 512) ? W_ih2[(size_t)cb * 512 + k]
                                : W_hh2[(size_t)cb * 128 + (k - 512)];
            g_W2p[(size_t)i2 * 640 + k] = __float2half(v);
        }
    }
}

__global__ __launch_bounds__(256) void pb_kernel(
    const float* __restrict__ emb, const float* __restrict__ W_ih1,
    const float* __restrict__ b_ih1, const float* __restrict__ b_hh1)
{
    const int ca = blockIdx.x * 32 + (threadIdx.x & 31);
    const int rg = threadIdx.x >> 5;
    float acc[8];
#pragma unroll
    for (int i = 0; i < 8; i++) acc[i] = 0.0f;
    for (int k = 0; k < HH; k++) {
        float w = W_ih1[(size_t)ca * 640 + k];
#pragma unroll
        for (int i = 0; i < 8; i++) acc[i] = fmaf(emb[(size_t)(rg * 8 + i) * HH + k], w, acc[i]);
    }
    float bb = b_ih1[ca] + b_hh1[ca];
#pragma unroll
    for (int i = 0; i < 8; i++) g_PbT[(size_t)ca * 64 + rg * 8 + i] = acc[i] + bb;
}

__global__ __launch_bounds__(NTHR, 2) void decoder_main(
    const int* __restrict__ text,
    const float* __restrict__ b_ih2, const float* __restrict__ b_hh2,
    const float* __restrict__ W_mos, const float* __restrict__ b_mos,
    float* __restrict__ out)
{
    extern __shared__ __align__(16) char sm[];
    __half* W1s = (__half*)(sm + OFF_W1);
    __half* W2s = (__half*)(sm + OFF_W2);
    __half* Xs  = (__half*)(sm + OFF_XS);
    float*  sgA = (float*)(sm + OFF_U);
    float*  sgB = (float*)(sm + OFF_U);
    SCt&    sc  = *(SCt*)(sm + OFF_U);
    __shared__ int toks[64];

    const int blk = blockIdx.x, tid = threadIdx.x;
    const int w = tid >> 5, lane = tid & 31;
    const uint32_t uW1 = cvta_s(W1s), uW2 = cvta_s(W2s), uXs = cvta_s(Xs);

    {   // persistent weight tiles -> smem
        const int ct = blk >> 1;
        for (int s = tid; s < 1280; s += 256) {
            int r = s / 80, seg = s - r * 80;
            *(uint4*)&W1s[r * WST + seg * 8] = *(const uint4*)&g_W1p[(size_t)(ct * 16 + r) * 640 + seg * 8];
        }
        if (blk < 32) {
            for (int s = tid; s < 1280; s += 256) {
                int r = s / 80, seg = s - r * 80;
                *(uint4*)&W2s[r * WST + seg * 8] = *(const uint4*)&g_W2p[(size_t)(blk * 16 + r) * 640 + seg * 8];
            }
        }
    }
    __syncthreads();

    for (int l = 0; l < LL; l++) {
        const int q = l & 1;

        // ===== phase A: LSTM1 gates (16 gate-rows x 64 n) via HMMA =====
        {
            const int ct = blk >> 1, nh = blk & 1;
            if (tid < 64) toks[tid] = text[((nh << 6) + tid) * LL + l];
            const __half* x1p = g_x1[q];
            float d0 = 0.f, d1 = 0.f, d2 = 0.f, d3 = 0.f;
            const int sr = tid >> 2, sseg = tid & 3;
            const uint32_t aOfs = (uint32_t)(lane & 15) * WST + ((lane >> 4) << 3);
#pragma unroll 1
            for (int ch = 0; ch < 10; ch++) {
                __syncthreads();
                const __half* src = x1p + (((ch << 6) + sr) << 7) + (nh << 6);
                *(uint4*)&Xs[sr * XST + sseg * 8]      = *(const uint4*)(src + sseg * 8);
                *(uint4*)&Xs[sr * XST + 32 + sseg * 8] = *(const uint4*)(src + 32 + sseg * 8);
                __syncthreads();
#pragma unroll
                for (int ks = 0; ks < 4; ks++) {
                    uint32_t a0, a1, a2, a3, b0, b1;
                    ldsm_x4(a0, a1, a2, a3, uW1 + (aOfs + (ch << 6) + (ks << 4)) * 2);
                    ldsm_x2t(b0, b1, uXs + ((((ks << 4) + (lane & 15)) * XST) + (w << 3)) * 2);
                    mma16816(d0, d1, d2, d3, a0, a1, a2, a3, b0, b1);
                }
            }
            __syncthreads();
            {
                int r = lane >> 2, c = (w << 3) + ((lane & 3) << 1);
                sgA[r * 68 + c] = d0;       sgA[r * 68 + c + 1] = d1;
                sgA[(r + 8) * 68 + c] = d2; sgA[(r + 8) * 68 + c + 1] = d3;
            }
            __syncthreads();
            {
                const int u = tid >> 6, an = tid & 63, n = ((blk & 1) << 6) + an;
                const int tok = toks[an];
                const int base = ct * 4 + u;
                float gi = sgA[(4 * u + 0) * 68 + an] + g_PbT[(size_t)(base) * 64 + tok];
                float gf = sgA[(4 * u + 1) * 68 + an] + g_PbT[(size_t)(512 + base) * 64 + tok];
                float gg = sgA[(4 * u + 2) * 68 + an] + g_PbT[(size_t)(1024 + base) * 64 + tok];
                float go = sgA[(4 * u + 3) * 68 + an] + g_PbT[(size_t)(1536 + base) * 64 + tok];
                const int ci = (base << 7) + n;
                float cn = sigf(gf) * g_c1[ci] + sigf(gi) * tanhf(gg);
                g_c1[ci] = cn;
                __half hval = __float2half(sigf(go) * tanhf(cn));
                g_x1[q ^ 1][((128 + base) << 7) + n] = hval;
                g_x2[q ^ 1][(base << 7) + n] = hval;
            }
        }
        gbar();

        // ===== phase B: LSTM2 gates (blocks<32; 16 gate-rows x 128 n) =====
        if (blk < 32) {
            const __half* x2p = g_x2[q ^ 1];
            float e0 = 0.f, e1 = 0.f, e2 = 0.f, e3 = 0.f;
            float f0 = 0.f, f1 = 0.f, f2 = 0.f, f3 = 0.f;
            const int sr = tid >> 2, sseg = tid & 3;
            const uint32_t aOfs = (uint32_t)(lane & 15) * WST + ((lane >> 4) << 3);
#pragma unroll 1
            for (int ch = 0; ch < 10; ch++) {
                __syncthreads();
                const __half* src = x2p + (((ch << 6) + sr) << 7) + sseg * 32;
#pragma unroll
                for (int j = 0; j < 4; j++)
                    *(uint4*)&Xs[sr * XST + sseg * 32 + j * 8] = *(const uint4*)(src + j * 8);
                __syncthreads();
#pragma unroll
                for (int ks = 0; ks < 4; ks++) {
                    uint32_t a0, a1, a2, a3, b0, b1, b2, b3;
                    ldsm_x4(a0, a1, a2, a3, uW2 + (aOfs + (ch << 6) + (ks << 4)) * 2);
                    ldsm_x4t(b0, b1, b2, b3,
                        uXs + ((((ks << 4) + (lane & 15)) * XST) + (w << 4) + ((lane >> 4) << 3)) * 2);
                    mma16816(e0, e1, e2, e3, a0, a1, a2, a3, b0, b1);
                    mma16816(f0, f1, f2, f3, a0, a1, a2, a3, b2, b3);
                }
            }
            __syncthreads();
            {
                int r = lane >> 2, c = (w << 4) + ((lane & 3) << 1);
                sgB[r * 136 + c] = e0;           sgB[r * 136 + c + 1] = e1;
                sgB[(r + 8) * 136 + c] = e2;     sgB[(r + 8) * 136 + c + 1] = e3;
                sgB[r * 136 + c + 8] = f0;       sgB[r * 136 + c + 9] = f1;
                sgB[(r + 8) * 136 + c + 8] = f2; sgB[(r + 8) * 136 + c + 9] = f3;
            }
            __syncthreads();
#pragma unroll
            for (int j = 0; j < 2; j++) {
                int idx = tid + (j << 8);
                int u = idx >> 7, n = idx & 127;
                int base = blk * 4 + u;
                float gi = sgB[(4 * u + 0) * 136 + n] + b_ih2[base]       + b_hh2[base];
                float gf = sgB[(4 * u + 1) * 136 + n] + b_ih2[128 + base] + b_hh2[128 + base];
                float gg = sgB[(4 * u + 2) * 136 + n] + b_ih2[256 + base] + b_hh2[256 + base];
                float go = sgB[(4 * u + 3) * 136 + n] + b_ih2[384 + base] + b_hh2[384 + base];
                int ci = (base << 7) + n;
                float cn = sigf(gf) * g_c2[ci] + sigf(gi) * tanhf(gg);
                g_c2[ci] = cn;
                float h2v = sigf(go) * tanhf(cn);
                g_h2N[(n << 7) + base] = h2v;
                g_x2[q][((512 + base) << 7) + n] = __float2half(h2v);
            }
        }
        gbar();

        // ===== phase C: balanced flash attention + combine + MoS =====
        {
            if (tid <= NB) sc.prefix[tid] = g_prefix[tid];
            __syncthreads();
            const long long W = sc.prefix[NB];
            const int r0 = (int)((long long)blk * W / NBLK);
            const int r1 = (int)((long long)(blk + 1) * W / NBLK);

            int n0 = 0;
            for (int n = 1; n < NB; n++) { if (sc.prefix[n] <= r0) n0 = n; else break; }

            for (int n = n0; n < NB && sc.prefix[n] < r1; n++) {
                const int Pn = sc.prefix[n], Pn1 = sc.prefix[n + 1];
                const int tlo = max(r0, Pn) - Pn;
                const int thi = min(r1, Pn1) - Pn;
                if (thi <= tlo) continue;

                if (tid < KK) sc.h2s[tid] = __ldcg(&g_h2N[(n << 7) + tid]);
                __syncthreads();
                const float4 hv = *(const float4*)&sc.h2s[lane << 2];

                float m = -1e30f, ssum = 0.0f;
                float4 acc = make_float4(0.f, 0.f, 0.f, 0.f);
                const __half* kbase = g_kb + (size_t)n * TT * 128 + (lane << 2);
                const __half* vbase = g_vb + (size_t)n * TT * 128 + (lane << 2);

                int t = tlo + w;
                for (; t + 24 < thi; t += 32) {
                    const __half* kp = kbase + (size_t)t * 128;
                    const __half* vp = vbase + (size_t)t * 128;
                    uint2 kw0 = *(const uint2*)kp;
                    uint2 kw1 = *(const uint2*)(kp + 1024);
                    uint2 kw2 = *(const uint2*)(kp + 2048);
                    uint2 kw3 = *(const uint2*)(kp + 3072);
                    uint2 vw0 = *(const uint2*)vp;
                    uint2 vw1 = *(const uint2*)(vp + 1024);
                    uint2 vw2 = *(const uint2*)(vp + 2048);
                    uint2 vw3 = *(const uint2*)(vp + 3072);
                    float2 a0 = __half22float2(*(__half2*)&kw0.x);
                    float2 b0 = __half22float2(*(__half2*)&kw0.y);
                    float2 a1 = __half22float2(*(__half2*)&kw1.x);
                    float2 b1 = __half22float2(*(__half2*)&kw1.y);
                    float2 a2 = __half22float2(*(__half2*)&kw2.x);
                    float2 b2 = __half22float2(*(__half2*)&kw2.y);
                    float2 a3 = __half22float2(*(__half2*)&kw3.x);
                    float2 b3 = __half22float2(*(__half2*)&kw3.y);
                    float d0 = a0.x * hv.x + a0.y * hv.y + b0.x * hv.z + b0.y * hv.w;
                    float d1 = a1.x * hv.x + a1.y * hv.y + b1.x * hv.z + b1.y * hv.w;
                    float d2 = a2.x * hv.x + a2.y * hv.y + b2.x * hv.z + b2.y * hv.w;
                    float d3 = a3.x * hv.x + a3.y * hv.y + b3.x * hv.z + b3.y * hv.w;
#pragma unroll
                    for (int o = 16; o; o >>= 1) {
                        d0 += __shfl_xor_sync(0xffffffffu, d0, o);
                        d1 += __shfl_xor_sync(0xffffffffu, d1, o);
                        d2 += __shfl_xor_sync(0xffffffffu, d2, o);
                        d3 += __shfl_xor_sync(0xffffffffu, d3, o);
                    }
                    float mx = fmaxf(fmaxf(d0, d1), fmaxf(d2, d3));
                    float mn = fmaxf(m, mx);
                    float scale = __expf(m - mn);
                    float p0 = __expf(d0 - mn), p1 = __expf(d1 - mn);
                    float p2 = __expf(d2 - mn), p3 = __expf(d3 - mn);
                    ssum = ssum * scale + ((p0 + p1) + (p2 + p3));
                    float2 va0 = __half22float2(*(__half2*)&vw0.x);
                    float2 vb0 = __half22float2(*(__half2*)&vw0.y);
                    float2 va1 = __half22float2(*(__half2*)&vw1.x);
                    float2 vb1 = __half22float2(*(__half2*)&vw1.y);
                    float2 va2 = __half22float2(*(__half2*)&vw2.x);
                    float2 vb2 = __half22float2(*(__half2*)&vw2.y);
                    float2 va3 = __half22float2(*(__half2*)&vw3.x);
                    float2 vb3 = __half22float2(*(__half2*)&vw3.y);
                    acc.x = acc.x * scale + p0 * va0.x + p1 * va1.x + p2 * va2.x + p3 * va3.x;
                    acc.y = acc.y * scale + p0 * va0.y + p1 * va1.y + p2 * va2.y + p3 * va3.y;
                    acc.z = acc.z * scale + p0 * vb0.x + p1 * vb1.x + p2 * vb2.x + p3 * vb3.x;
                    acc.w = acc.w * scale + p0 * vb0.y + p1 * vb1.y + p2 * vb2.y + p3 * vb3.y;
                    m = mn;
                }
                for (; t < thi; t += 8) {
                    const __half* kp = kbase + (size_t)t * 128;
                    const __half* vp = vbase + (size_t)t * 128;
                    uint2 kw = *(const uint2*)kp;
                    uint2 vw = *(const uint2*)vp;
                    float2 a0 = __half22float2(*(__half2*)&kw.x);
                    float2 b0 = __half22float2(*(__half2*)&kw.y);
                    float d = a0.x * hv.x + a0.y * hv.y + b0.x * hv.z + b0.y * hv.w;
#pragma unroll
                    for (int o = 16; o; o >>= 1) d += __shfl_xor_sync(0xffffffffu, d, o);
                    float mn = fmaxf(m, d);
                    float scale = __expf(m - mn);
                    float pp = __expf(d - mn);
                    ssum = ssum * scale + pp;
                    float2 va = __half22float2(*(__half2*)&vw.x);
                    float2 vb = __half22float2(*(__half2*)&vw.y);
                    acc.x = acc.x * scale + pp * va.x;
                    acc.y = acc.y * scale + pp * va.y;
                    acc.z = acc.z * scale + pp * vb.x;
                    acc.w = acc.w * scale + pp * vb.y;
                    m = mn;
                }

                if (lane == 0) { sc.wm[w] = m; sc.wsum[w] = ssum; }
                *(float4*)&sc.wacc[w][lane << 2] = acc;
                __syncthreads();

                const int slot = blk - g_bfirst[n];
                if (tid < VV) {
                    float mm = -1e30f;
#pragma unroll
                    for (int ww = 0; ww < 8; ww++) mm = fmaxf(mm, sc.wm[ww]);
                    float S = 0.0f, C = 0.0f;
#pragma unroll
                    for (int ww = 0; ww < 8; ww++) {
                        float e = __expf(sc.wm[ww] - mm);
                        S += e * sc.wsum[ww];
                        C += e * sc.wacc[ww][tid];
                    }
                    g_pacc[((size_t)n * NBLK + slot) * VV + tid] = C;
                    if (tid == 0) { g_pm[n * NBLK + slot] = mm; g_ps[n * NBLK + slot] = S; }
                    __threadfence();
                }
                __syncthreads();
                if (tid == 0) {
                    int old = atomicAdd(&g_acnt[n], 1);
                    __threadfence();
                    sc.flag = (old == g_bcnt[n] - 1);
                }
                __syncthreads();
                if (sc.flag) {
                    const int bf = g_bfirst[n], bl = g_blast[n];
                    if (tid < VV) {
                        float mm = -1e30f;
                        for (int bb = bf; bb <= bl; bb++) {
                            int rr0 = (int)((long long)bb * W / NBLK);
                            int rr1 = (int)((long long)(bb + 1) * W / NBLK);
                            if (max(rr0, Pn) < min(rr1, Pn1))
                                mm = fmaxf(mm, __ldcg(&g_pm[n * NBLK + (bb - bf)]));
                        }
                        float S = 0.0f, C = 0.0f;
                        for (int bb = bf; bb <= bl; bb++) {
                            int rr0 = (int)((long long)bb * W / NBLK);
                            int rr1 = (int)((long long)(bb + 1) * W / NBLK);
                            if (max(rr0, Pn) < min(rr1, Pn1)) {
                                int s2 = bb - bf;
                                float e = __expf(__ldcg(&g_pm[n * NBLK + s2]) - mm);
                                S += e * __ldcg(&g_ps[n * NBLK + s2]);
                                C += e * __ldcg(&g_pacc[((size_t)n * NBLK + s2) * VV + tid]);
                            }
                        }
                        float cv = C / S;
                        sc.ctxs[tid] = cv;
                        g_x1[q ^ 1][(tid << 7) + n] = __float2half(cv);
                    }
                    if (tid == 0) g_acnt[n] = 0;
                    __syncthreads();
                    if (tid < AA) {
                        float a = b_mos[tid];
                        const float* wr = W_mos + (size_t)tid * (KK + VV);
#pragma unroll 4
                        for (int k = 0; k < KK; k++) a = fmaf(sc.h2s[k], wr[k], a);
#pragma unroll 4
                        for (int v = 0; v < VV; v++) a = fmaf(sc.ctxs[v], wr[KK + v], a);
                        out[((size_t)n * LL + l) * AA + tid] = a;
                    }
                }
                __syncthreads();
            }
        }
        gbar();
    }
}

extern "C" void kernel_launch(void* const* d_in, const int* in_sizes, int n_in,
                              void* d_out, int out_size) {
    (void)in_sizes; (void)n_in; (void)out_size;
    const float* key    = (const float*)d_in[0];
    const float* values = (const float*)d_in[1];
    const int*   lens   = (const int*)  d_in[2];
    const int*   text   = (const int*)  d_in[3];
    const float* emb    = (const float*)d_in[4];
    const float* W_ih1  = (const float*)d_in[5];
    const float* W_hh1  = (const float*)d_in[6];
    const float* b_ih1  = (const float*)d_in[7];
    const float* b_hh1  = (const float*)d_in[8];
    const float* W_ih2  = (const float*)d_in[9];
    const float* W_hh2  = (const float*)d_in[10];
    const float* b_ih2  = (const float*)d_in[11];
    const float* b_hh2  = (const float*)d_in[12];
    const float* W_mos  = (const float*)d_in[13];
    const float* b_mos  = (const float*)d_in[14];
    float* out = (float*)d_out;

    static int s_attr = 0;
    if (!s_attr) {
        cudaFuncSetAttribute(decoder_main, cudaFuncAttributeMaxDynamicSharedMemorySize, SMEM_TOTAL);
        s_attr = 1;
    }
    init2_kernel<<<512, 256>>>(values);
    meta_kernel<<<1, 256>>>(lens);
    convkv_kernel<<<32000, 256>>>(key, values);
    convw_kernel<<<2560, 256>>>(W_ih1, W_hh1, W_ih2, W_hh2);
    pb_kernel<<<64, 256>>>(emb, W_ih1, b_ih1, b_hh1);
    decoder_main<<<NBLK, NTHR, SMEM_TOTAL>>>(text, b_ih2, b_hh2, W_mos, b_mos, out);
}

// round 9
// speedup vs baseline: 1.6109x; 1.0928x over previous
#include <cuda_runtime.h>
#include <cuda_fp16.h>
#include <math.h>
#include <stdint.h>

#define NB 128
#define TT 2000
#define LL 250
#define HH 512
#define KK 128
#define VV 128
#define AA 64
#define NBLK 256
#define NTHR 256

__device__ __align__(16) __half g_kb[(size_t)NB * TT * 128];
__device__ __align__(16) __half g_vb[(size_t)NB * TT * 128];
__device__ __align__(16) __half g_W1p[2048 * 640];
__device__ __align__(16) __half g_W2p[512 * 640];
__device__ __align__(16) __half g_x1[2][640 * 128];   // rows: 0-127 ctx, 128-639 h1
__device__ __align__(16) __half g_x2[2][640 * 128];   // rows: 0-511 h1, 512-639 h2
__device__ float g_h2N[128 * 128];
__device__ float g_PbT[2048 * 64];
__device__ float g_c1[512 * 128], g_c2[128 * 128];
__device__ float g_pm[NB * NBLK], g_ps[NB * NBLK];
__device__ float g_pacc[(size_t)NB * NBLK * VV];
__device__ int   g_acnt[NB];
__device__ int   g_prefix[NB + 1];
__device__ int   g_bfirst[NB], g_blast[NB], g_bcnt[NB];
__device__ unsigned g_gen, g_cnt;

struct SCt {
    float h2s[128];
    float wacc[8][128];
    float ctxs[128];
    float wm[8], wsum[8];
    int   flag;
};

#define OFF_W1 0
#define OFF_W2 21248
#define OFF_XS 42496
#define OFF_U  59904
#define SMEM_TOTAL 68608
#define WST 664
#define XST 136

__device__ __forceinline__ float sigf(float x) { return 1.0f / (1.0f + __expf(-x)); }
__device__ __forceinline__ uint32_t cvta_s(const void* p) { return (uint32_t)__cvta_generic_to_shared(p); }
__device__ __forceinline__ void ldsm_x4(uint32_t& a0, uint32_t& a1, uint32_t& a2, uint32_t& a3, uint32_t a) {
    asm volatile("ldmatrix.sync.aligned.m8n8.x4.shared.b16 {%0,%1,%2,%3},[%4];"
        : "=r"(a0), "=r"(a1), "=r"(a2), "=r"(a3) : "r"(a));
}
__device__ __forceinline__ void ldsm_x2t(uint32_t& b0, uint32_t& b1, uint32_t a) {
    asm volatile("ldmatrix.sync.aligned.m8n8.x2.trans.shared.b16 {%0,%1},[%2];"
        : "=r"(b0), "=r"(b1) : "r"(a));
}
__device__ __forceinline__ void mma16816(float& d0, float& d1, float& d2, float& d3,
    uint32_t a0, uint32_t a1, uint32_t a2, uint32_t a3, uint32_t b0, uint32_t b1) {
    asm volatile("mma.sync.aligned.m16n8k16.row.col.f32.f16.f16.f32 "
        "{%0,%1,%2,%3},{%4,%5,%6,%7},{%8,%9},{%0,%1,%2,%3};"
        : "+f"(d0), "+f"(d1), "+f"(d2), "+f"(d3)
        : "r"(a0), "r"(a1), "r"(a2), "r"(a3), "r"(b0), "r"(b1));
}

__device__ __forceinline__ void gbar() {
    __syncthreads();
    __threadfence();
    if (threadIdx.x == 0) {
        unsigned my = *(volatile unsigned*)&g_gen;
        unsigned old = atomicAdd(&g_cnt, 1u);
        if (old == NBLK - 1) { g_cnt = 0u; __threadfence(); atomicAdd(&g_gen, 1u); }
        else { while (*(volatile unsigned*)&g_gen == my) { __nanosleep(64); } }
        __threadfence();
    }
    __syncthreads();
}

// ---- launch 1: init state + meta ----
__global__ void setup_a(const float* __restrict__ values, const int* __restrict__ lens) {
    if (blockIdx.x == 0) {
        __shared__ int pre[NB + 1];
        if (threadIdx.x == 0) {
            int s = 0;
            for (int n = 0; n < NB; n++) { pre[n] = s; s += lens[n]; }
            pre[NB] = s;
            for (int i = 0; i <= NB; i++) g_prefix[i] = pre[i];
        }
        __syncthreads();
        int n = threadIdx.x;
        if (n < NB) {
            long long W = pre[NB];
            int Pn = pre[n], Pn1 = pre[n + 1], bf = 0, bl = 0, cnt = 0;
            for (int b = 0; b < NBLK; b++) {
                int r0 = (int)((long long)b * W / NBLK);
                int r1 = (int)((long long)(b + 1) * W / NBLK);
                if (max(r0, Pn) < min(r1, Pn1)) { if (cnt == 0) bf = b; bl = b; cnt++; }
            }
            g_bfirst[n] = bf; g_blast[n] = bl; g_bcnt[n] = cnt;
        }
        return;
    }
    int i = (blockIdx.x - 1) * 256 + threadIdx.x;   // 512 worker blocks
    if (i < 512 * 128) g_c1[i] = 0.0f;
    if (i < 128 * 128) { g_c2[i] = 0.0f; g_x2[1][512 * 128 + i] = __float2half(0.0f); }
    if (i < 640 * 128) {
        int k = i >> 7, n = i & 127;
        g_x1[0][i] = (k < 128) ? __float2half(values[n * 128 + k]) : __float2half(0.0f);
    }
    if (i < NB) g_acnt[i] = 0;
}

// ---- launch 2: K/V transpose to [n][t][f] fp16 ----
__global__ void convkv_kernel(const float* __restrict__ key, const float* __restrict__ val) {
    int rid = blockIdx.x * 8 + (threadIdx.x >> 5);
    int lane = threadIdx.x & 31;
    if (rid < TT * NB) {
        int t = rid >> 7, n = rid & 127;
        float4 kv = *(const float4*)(key + ((size_t)rid << 7) + (lane << 2));
        float4 vv = *(const float4*)(val + ((size_t)rid << 7) + (lane << 2));
        size_t dst = ((size_t)n * TT + t) * 128 + (lane << 2);
        ((__half2*)(g_kb + dst))[0] = __floats2half2_rn(kv.x, kv.y);
        ((__half2*)(g_kb + dst))[1] = __floats2half2_rn(kv.z, kv.w);
        ((__half2*)(g_vb + dst))[0] = __floats2half2_rn(vv.x, vv.y);
        ((__half2*)(g_vb + dst))[1] = __floats2half2_rn(vv.z, vv.w);
    }
}

// ---- launch 3: weight permute/convert + PbT ----
__global__ void setup_b(const float* __restrict__ W_ih1, const float* __restrict__ W_hh1,
                        const float* __restrict__ W_ih2, const float* __restrict__ W_hh2,
                        const float* __restrict__ emb,
                        const float* __restrict__ b_ih1, const float* __restrict__ b_hh1) {
    int idx = blockIdx.x;    // 2624 blocks
    if (idx < 2048) {
        int ct = idx >> 4, r = idx & 15;
        int ca = ((r & 3) << 9) + ct * 4 + (r >> 2);
        for (int k = threadIdx.x; k < 640; k += 256) {
            float v = (k < 128) ? W_ih1[(size_t)ca * 640 + 512 + k]
                                : W_hh1[(size_t)ca * 512 + (k - 128)];
            g_W1p[(size_t)idx * 640 + k] = __float2half(v);
        }
    } else if (idx < 2560) {
        int i2 = idx - 2048, ct = i2 >> 4, r = i2 & 15;
        int cb = ((r & 3) << 7) + ct * 4 + (r >> 2);
        for (int k = threadIdx.x; k < 640; k += 256) {
            float v = (k < 512) ? W_ih2[(size_t)cb * 512 + k]
                                : W_hh2[(size_t)cb * 128 + (k - 512)];
            g_W2p[(size_t)i2 * 640 + k] = __float2half(v);
        }
    } else {
        const int ca = (idx - 2560) * 32 + (threadIdx.x & 31);
        const int rg = threadIdx.x >> 5;
        float acc[8];
#pragma unroll
        for (int i = 0; i < 8; i++) acc[i] = 0.0f;
        for (int k = 0; k < HH; k++) {
            float w = W_ih1[(size_t)ca * 640 + k];
#pragma unroll
            for (int i = 0; i < 8; i++) acc[i] = fmaf(emb[(size_t)(rg * 8 + i) * HH + k], w, acc[i]);
        }
        float bb = b_ih1[ca] + b_hh1[ca];
#pragma unroll
        for (int i = 0; i < 8; i++) g_PbT[(size_t)ca * 64 + rg * 8 + i] = acc[i] + bb;
    }
}

// ---- launch 4: persistent decoder (profiled by ncu) ----
__global__ __launch_bounds__(NTHR, 2) void decoder_main(
    const int* __restrict__ text,
    const float* __restrict__ b_ih2, const float* __restrict__ b_hh2,
    const float* __restrict__ W_mos, const float* __restrict__ b_mos,
    float* __restrict__ out)
{
    extern __shared__ __align__(16) char sm[];
    __half* W1s = (__half*)(sm + OFF_W1);
    __half* W2s = (__half*)(sm + OFF_W2);
    __half* Xs  = (__half*)(sm + OFF_XS);
    float*  sgA = (float*)(sm + OFF_U);
    SCt&    sc  = *(SCt*)(sm + OFF_U);
    __shared__ int toks[64];
    __shared__ int s_pre[NB + 1];

    const int blk = blockIdx.x, tid = threadIdx.x;
    const int w = tid >> 5, lane = tid & 31;
    const uint32_t uW1 = cvta_s(W1s), uW2 = cvta_s(W2s), uXs = cvta_s(Xs);

    {   // persistent weight tiles -> smem
        const int ct = blk >> 1;
        for (int s = tid; s < 1280; s += 256) {
            int r = s / 80, seg = s - r * 80;
            *(uint4*)&W1s[r * WST + seg * 8] = *(const uint4*)&g_W1p[(size_t)(ct * 16 + r) * 640 + seg * 8];
        }
        if (blk < 64) {
            const int bt = blk >> 1;
            for (int s = tid; s < 1280; s += 256) {
                int r = s / 80, seg = s - r * 80;
                *(uint4*)&W2s[r * WST + seg * 8] = *(const uint4*)&g_W2p[(size_t)(bt * 16 + r) * 640 + seg * 8];
            }
        }
        for (int i = tid; i <= NB; i += 256) s_pre[i] = g_prefix[i];
    }
    __syncthreads();

    // loop-invariant attention partition
    const long long Wtot = s_pre[NB];
    const int r0 = (int)((long long)blk * Wtot / NBLK);
    const int r1 = (int)((long long)(blk + 1) * Wtot / NBLK);
    int n0 = 0;
    for (int n = 1; n < NB; n++) { if (s_pre[n] <= r0) n0 = n; else break; }

    const int sr = tid >> 2, sseg = tid & 3;
    const uint32_t aOfs = (uint32_t)(lane & 15) * WST + ((lane >> 4) << 3);
    const uint32_t stO0 = (uint32_t)(sr * XST + sseg * 8);
    const uint32_t stO1 = stO0 + 32;

    for (int l = 0; l < LL; l++) {
        const int q = l & 1;

        // ===== phase A: LSTM1 gates (16 gate-rows x 64 n) via HMMA =====
        {
            const int ct = blk >> 1, nh = blk & 1;
            if (tid < 64) toks[tid] = text[((nh << 6) + tid) * LL + l];
            const __half* x1p = g_x1[q] + (nh << 6);
            float d0 = 0.f, d1 = 0.f, d2 = 0.f, d3 = 0.f;
            uint4 pf0, pf1;
            {
                const __half* s = x1p + (sr << 7);
                pf0 = *(const uint4*)(s + sseg * 8);
                pf1 = *(const uint4*)(s + 32 + sseg * 8);
            }
#pragma unroll 1
            for (int ch = 0; ch < 10; ch++) {
                __syncthreads();
                *(uint4*)&Xs[stO0] = pf0;
                *(uint4*)&Xs[stO1] = pf1;
                __syncthreads();
                if (ch < 9) {
                    const __half* s = x1p + ((((ch + 1) << 6) + sr) << 7);
                    pf0 = *(const uint4*)(s + sseg * 8);
                    pf1 = *(const uint4*)(s + 32 + sseg * 8);
                }
#pragma unroll
                for (int ks = 0; ks < 4; ks++) {
                    uint32_t a0, a1, a2, a3, b0, b1;
                    ldsm_x4(a0, a1, a2, a3, uW1 + (aOfs + (ch << 6) + (ks << 4)) * 2);
                    ldsm_x2t(b0, b1, uXs + ((((ks << 4) + (lane & 15)) * XST) + (w << 3)) * 2);
                    mma16816(d0, d1, d2, d3, a0, a1, a2, a3, b0, b1);
                }
            }
            __syncthreads();
            {
                int r = lane >> 2, c = (w << 3) + ((lane & 3) << 1);
                sgA[r * 68 + c] = d0;       sgA[r * 68 + c + 1] = d1;
                sgA[(r + 8) * 68 + c] = d2; sgA[(r + 8) * 68 + c + 1] = d3;
            }
            __syncthreads();
            {
                const int u = tid >> 6, an = tid & 63, n = (nh << 6) + an;
                const int tok = toks[an];
                const int base = ct * 4 + u;
                float gi = sgA[(4 * u + 0) * 68 + an] + g_PbT[(size_t)(base) * 64 + tok];
                float gf = sgA[(4 * u + 1) * 68 + an] + g_PbT[(size_t)(512 + base) * 64 + tok];
                float gg = sgA[(4 * u + 2) * 68 + an] + g_PbT[(size_t)(1024 + base) * 64 + tok];
                float go = sgA[(4 * u + 3) * 68 + an] + g_PbT[(size_t)(1536 + base) * 64 + tok];
                const int ci = (base << 7) + n;
                float cn = sigf(gf) * g_c1[ci] + sigf(gi) * tanhf(gg);
                g_c1[ci] = cn;
                __half hval = __float2half(sigf(go) * tanhf(cn));
                g_x1[q ^ 1][((128 + base) << 7) + n] = hval;
                g_x2[q ^ 1][(base << 7) + n] = hval;
            }
        }
        gbar();

        // ===== phase B: LSTM2 gates (64 blocks; 16 gate-rows x 64 n) =====
        if (blk < 64) {
            const int bt = blk >> 1, nh = blk & 1;
            const __half* x2p = g_x2[q ^ 1] + (nh << 6);
            float d0 = 0.f, d1 = 0.f, d2 = 0.f, d3 = 0.f;
            uint4 pf0, pf1;
            {
                const __half* s = x2p + (sr << 7);
                pf0 = *(const uint4*)(s + sseg * 8);
                pf1 = *(const uint4*)(s + 32 + sseg * 8);
            }
#pragma unroll 1
            for (int ch = 0; ch < 10; ch++) {
                __syncthreads();
                *(uint4*)&Xs[stO0] = pf0;
                *(uint4*)&Xs[stO1] = pf1;
                __syncthreads();
                if (ch < 9) {
                    const __half* s = x2p + ((((ch + 1) << 6) + sr) << 7);
                    pf0 = *(const uint4*)(s + sseg * 8);
                    pf1 = *(const uint4*)(s + 32 + sseg * 8);
                }
#pragma unroll
                for (int ks = 0; ks < 4; ks++) {
                    uint32_t a0, a1, a2, a3, b0, b1;
                    ldsm_x4(a0, a1, a2, a3, uW2 + (aOfs + (ch << 6) + (ks << 4)) * 2);
                    ldsm_x2t(b0, b1, uXs + ((((ks << 4) + (lane & 15)) * XST) + (w << 3)) * 2);
                    mma16816(d0, d1, d2, d3, a0, a1, a2, a3, b0, b1);
                }
            }
            __syncthreads();
            {
                int r = lane >> 2, c = (w << 3) + ((lane & 3) << 1);
                sgA[r * 68 + c] = d0;       sgA[r * 68 + c + 1] = d1;
                sgA[(r + 8) * 68 + c] = d2; sgA[(r + 8) * 68 + c + 1] = d3;
            }
            __syncthreads();
            {
                const int u = tid >> 6, an = tid & 63, n = (nh << 6) + an;
                const int base = bt * 4 + u;
                float gi = sgA[(4 * u + 0) * 68 + an] + b_ih2[base]       + b_hh2[base];
                float gf = sgA[(4 * u + 1) * 68 + an] + b_ih2[128 + base] + b_hh2[128 + base];
                float gg = sgA[(4 * u + 2) * 68 + an] + b_ih2[256 + base] + b_hh2[256 + base];
                float go = sgA[(4 * u + 3) * 68 + an] + b_ih2[384 + base] + b_hh2[384 + base];
                const int ci = (base << 7) + n;
                float cn = sigf(gf) * g_c2[ci] + sigf(gi) * tanhf(gg);
                g_c2[ci] = cn;
                float h2v = sigf(go) * tanhf(cn);
                g_h2N[(n << 7) + base] = h2v;
                g_x2[q][((512 + base) << 7) + n] = __float2half(h2v);
            }
        }
        gbar();

        // ===== phase C: balanced flash attention + combine + MoS =====
        {
            for (int n = n0; n < NB && s_pre[n] < r1; n++) {
                const int Pn = s_pre[n], Pn1 = s_pre[n + 1];
                const int tlo = max(r0, Pn) - Pn;
                const int thi = min(r1, Pn1) - Pn;
                if (thi <= tlo) continue;

                if (tid < KK) sc.h2s[tid] = __ldcg(&g_h2N[(n << 7) + tid]);
                __syncthreads();
                const float4 hv = *(const float4*)&sc.h2s[lane << 2];

                float m = -1e30f, ssum = 0.0f;
                float4 acc = make_float4(0.f, 0.f, 0.f, 0.f);
                const __half* kbase = g_kb + (size_t)n * TT * 128 + (lane << 2);
                const __half* vbase = g_vb + (size_t)n * TT * 128 + (lane << 2);

                int t = tlo + w;
                for (; t + 24 < thi; t += 32) {
                    const __half* kp = kbase + (size_t)t * 128;
                    const __half* vp = vbase + (size_t)t * 128;
                    uint2 kw0 = *(const uint2*)kp;
                    uint2 kw1 = *(const uint2*)(kp + 1024);
                    uint2 kw2 = *(const uint2*)(kp + 2048);
                    uint2 kw3 = *(const uint2*)(kp + 3072);
                    uint2 vw0 = *(const uint2*)vp;
                    uint2 vw1 = *(const uint2*)(vp + 1024);
                    uint2 vw2 = *(const uint2*)(vp + 2048);
                    uint2 vw3 = *(const uint2*)(vp + 3072);
                    float2 a0 = __half22float2(*(__half2*)&kw0.x);
                    float2 b0 = __half22float2(*(__half2*)&kw0.y);
                    float2 a1 = __half22float2(*(__half2*)&kw1.x);
                    float2 b1 = __half22float2(*(__half2*)&kw1.y);
                    float2 a2 = __half22float2(*(__half2*)&kw2.x);
                    float2 b2 = __half22float2(*(__half2*)&kw2.y);
                    float2 a3 = __half22float2(*(__half2*)&kw3.x);
                    float2 b3 = __half22float2(*(__half2*)&kw3.y);
                    float d0 = a0.x * hv.x + a0.y * hv.y + b0.x * hv.z + b0.y * hv.w;
                    float d1 = a1.x * hv.x + a1.y * hv.y + b1.x * hv.z + b1.y * hv.w;
                    float d2 = a2.x * hv.x + a2.y * hv.y + b2.x * hv.z + b2.y * hv.w;
                    float d3 = a3.x * hv.x + a3.y * hv.y + b3.x * hv.z + b3.y * hv.w;
#pragma unroll
                    for (int o = 16; o; o >>= 1) {
                        d0 += __shfl_xor_sync(0xffffffffu, d0, o);
                        d1 += __shfl_xor_sync(0xffffffffu, d1, o);
                        d2 += __shfl_xor_sync(0xffffffffu, d2, o);
                        d3 += __shfl_xor_sync(0xffffffffu, d3, o);
                    }
                    float mx = fmaxf(fmaxf(d0, d1), fmaxf(d2, d3));
                    float mn = fmaxf(m, mx);
                    float scale = __expf(m - mn);
                    float p0 = __expf(d0 - mn), p1 = __expf(d1 - mn);
                    float p2 = __expf(d2 - mn), p3 = __expf(d3 - mn);
                    ssum = ssum * scale + ((p0 + p1) + (p2 + p3));
                    float2 va0 = __half22float2(*(__half2*)&vw0.x);
                    float2 vb0 = __half22float2(*(__half2*)&vw0.y);
                    float2 va1 = __half22float2(*(__half2*)&vw1.x);
                    float2 vb1 = __half22float2(*(__half2*)&vw1.y);
                    float2 va2 = __half22float2(*(__half2*)&vw2.x);
                    float2 vb2 = __half22float2(*(__half2*)&vw2.y);
                    float2 va3 = __half22float2(*(__half2*)&vw3.x);
                    float2 vb3 = __half22float2(*(__half2*)&vw3.y);
                    acc.x = acc.x * scale + p0 * va0.x + p1 * va1.x + p2 * va2.x + p3 * va3.x;
                    acc.y = acc.y * scale + p0 * va0.y + p1 * va1.y + p2 * va2.y + p3 * va3.y;
                    acc.z = acc.z * scale + p0 * vb0.x + p1 * vb1.x + p2 * vb2.x + p3 * vb3.x;
                    acc.w = acc.w * scale + p0 * vb0.y + p1 * vb1.y + p2 * vb2.y + p3 * vb3.y;
                    m = mn;
                }
                for (; t < thi; t += 8) {
                    const __half* kp = kbase + (size_t)t * 128;
                    const __half* vp = vbase + (size_t)t * 128;
                    uint2 kw = *(const uint2*)kp;
                    uint2 vw = *(const uint2*)vp;
                    float2 a0 = __half22float2(*(__half2*)&kw.x);
                    float2 b0 = __half22float2(*(__half2*)&kw.y);
                    float d = a0.x * hv.x + a0.y * hv.y + b0.x * hv.z + b0.y * hv.w;
#pragma unroll
                    for (int o = 16; o; o >>= 1) d += __shfl_xor_sync(0xffffffffu, d, o);
                    float mn = fmaxf(m, d);
                    float scale = __expf(m - mn);
                    float pp = __expf(d - mn);
                    ssum = ssum * scale + pp;
                    float2 va = __half22float2(*(__half2*)&vw.x);
                    float2 vb = __half22float2(*(__half2*)&vw.y);
                    acc.x = acc.x * scale + pp * va.x;
                    acc.y = acc.y * scale + pp * va.y;
                    acc.z = acc.z * scale + pp * vb.x;
                    acc.w = acc.w * scale + pp * vb.y;
                    m = mn;
                }

                if (lane == 0) { sc.wm[w] = m; sc.wsum[w] = ssum; }
                *(float4*)&sc.wacc[w][lane << 2] = acc;
                __syncthreads();

                const int slot = blk - g_bfirst[n];
                if (tid < VV) {
                    float mm = -1e30f;
#pragma unroll
                    for (int ww = 0; ww < 8; ww++) mm = fmaxf(mm, sc.wm[ww]);
                    float S = 0.0f, C = 0.0f;
#pragma unroll
                    for (int ww = 0; ww < 8; ww++) {
                        float e = __expf(sc.wm[ww] - mm);
                        S += e * sc.wsum[ww];
                        C += e * sc.wacc[ww][tid];
                    }
                    g_pacc[((size_t)n * NBLK + slot) * VV + tid] = C;
                    if (tid == 0) { g_pm[n * NBLK + slot] = mm; g_ps[n * NBLK + slot] = S; }
                    __threadfence();
                }
                __syncthreads();
                if (tid == 0) {
                    int old = atomicAdd(&g_acnt[n], 1);
                    __threadfence();
                    sc.flag = (old == g_bcnt[n] - 1);
                }
                __syncthreads();
                if (sc.flag) {
                    const int bf = g_bfirst[n], bl = g_blast[n];
                    if (tid < VV) {
                        float mm = -1e30f;
                        for (int bb = bf; bb <= bl; bb++) {
                            int rr0 = (int)((long long)bb * Wtot / NBLK);
                            int rr1 = (int)((long long)(bb + 1) * Wtot / NBLK);
                            if (max(rr0, Pn) < min(rr1, Pn1))
                                mm = fmaxf(mm, __ldcg(&g_pm[n * NBLK + (bb - bf)]));
                        }
                        float S = 0.0f, C = 0.0f;
                        for (int bb = bf; bb <= bl; bb++) {
                            int rr0 = (int)((long long)bb * Wtot / NBLK);
                            int rr1 = (int)((long long)(bb + 1) * Wtot / NBLK);
                            if (max(rr0, Pn) < min(rr1, Pn1)) {
                                int s2 = bb - bf;
                                float e = __expf(__ldcg(&g_pm[n * NBLK + s2]) - mm);
                                S += e * __ldcg(&g_ps[n * NBLK + s2]);
                                C += e * __ldcg(&g_pacc[((size_t)n * NBLK + s2) * VV + tid]);
                            }
                        }
                        float cv = C / S;
                        sc.ctxs[tid] = cv;
                        g_x1[q ^ 1][(tid << 7) + n] = __float2half(cv);
                    }
                    if (tid == 0) g_acnt[n] = 0;
                    __syncthreads();
                    if (tid < AA) {
                        float a = b_mos[tid];
                        const float* wr = W_mos + (size_t)tid * (KK + VV);
#pragma unroll 4
                        for (int k = 0; k < KK; k++) a = fmaf(sc.h2s[k], wr[k], a);
#pragma unroll 4
                        for (int v = 0; v < VV; v++) a = fmaf(sc.ctxs[v], wr[KK + v], a);
                        out[((size_t)n * LL + l) * AA + tid] = a;
                    }
                }
                __syncthreads();
            }
        }
        gbar();
    }
}

extern "C" void kernel_launch(void* const* d_in, const int* in_sizes, int n_in,
                              void* d_out, int out_size) {
    (void)in_sizes; (void)n_in; (void)out_size;
    const float* key    = (const float*)d_in[0];
    const float* values = (const float*)d_in[1];
    const int*   lens   = (const int*)  d_in[2];
    const int*   text   = (const int*)  d_in[3];
    const float* emb    = (const float*)d_in[4];
    const float* W_ih1  = (const float*)d_in[5];
    const float* W_hh1  = (const float*)d_in[6];
    const float* b_ih1  = (const float*)d_in[7];
    const float* b_hh1  = (const float*)d_in[8];
    const float* W_ih2  = (const float*)d_in[9];
    const float* W_hh2  = (const float*)d_in[10];
    const float* b_ih2  = (const float*)d_in[11];
    const float* b_hh2  = (const float*)d_in[12];
    const float* W_mos  = (const float*)d_in[13];
    const float* b_mos  = (const float*)d_in[14];
    float* out = (float*)d_out;

    static int s_attr = 0;
    if (!s_attr) {
        cudaFuncSetAttribute(decoder_main, cudaFuncAttributeMaxDynamicSharedMemorySize, SMEM_TOTAL);
        s_attr = 1;
    }
    setup_a<<<513, 256>>>(values, lens);
    convkv_kernel<<<32000, 256>>>(key, values);
    setup_b<<<2624, 256>>>(W_ih1, W_hh1, W_ih2, W_hh2, emb, b_ih1, b_hh1);
    decoder_main<<<NBLK, NTHR, SMEM_TOTAL>>>(text, b_ih2, b_hh2, W_mos, b_mos, out);
}

// round 11
// speedup vs baseline: 1.6377x; 1.0167x over previous
#include <cuda_runtime.h>
#include <cuda_fp16.h>
#include <math.h>
#include <stdint.h>

#define NB 128
#define TT 2000
#define LL 250
#define HH 512
#define KK 128
#define VV 128
#define AA 64
#define NBLK 256
#define NTHR 512

__device__ __align__(16) __half g_kb[(size_t)NB * TT * 128];
__device__ __align__(16) __half g_vb[(size_t)NB * TT * 128];
__device__ __align__(16) __half g_W1p[2048 * 640];
__device__ __align__(16) __half g_W2p[512 * 640];
__device__ __align__(16) __half g_x1[2][640 * 128];   // rows: 0-127 ctx, 128-639 h1
__device__ __align__(16) __half g_x2[2][640 * 128];   // rows: 0-511 h1, 512-639 h2
__device__ float g_h2N[128 * 128];
__device__ float g_PbT[2048 * 64];
__device__ float g_c1[512 * 128], g_c2[128 * 128];
__device__ float g_pm[NB * NBLK], g_ps[NB * NBLK];
__device__ float g_pacc[(size_t)NB * NBLK * VV];
__device__ int   g_acnt[NB];
__device__ int   g_prefix[NB + 1];
__device__ int   g_bfirst[NB], g_blast[NB], g_bcnt[NB];
__device__ unsigned g_gen, g_cnt;

struct SCt {
    float h2s[128];
    float wacc[16][128];
    float ctxs[128];
    float wm[16], wsum[16];
    int   flag;
};

#define OFF_W1 0
#define OFF_W2 21248
#define OFF_XS 42496
#define OFF_U  77312
#define SMEM_TOTAL 87552
#define WST 664
#define XST 136
#define XBUF (64 * XST)      // halfs per Xs buffer

__device__ __forceinline__ float sigf(float x) { return 1.0f / (1.0f + __expf(-x)); }
__device__ __forceinline__ uint32_t cvta_s(const void* p) { return (uint32_t)__cvta_generic_to_shared(p); }
__device__ __forceinline__ void ldsm_x4(uint32_t& a0, uint32_t& a1, uint32_t& a2, uint32_t& a3, uint32_t a) {
    asm volatile("ldmatrix.sync.aligned.m8n8.x4.shared.b16 {%0,%1,%2,%3},[%4];"
        : "=r"(a0), "=r"(a1), "=r"(a2), "=r"(a3) : "r"(a));
}
__device__ __forceinline__ void ldsm_x2t(uint32_t& b0, uint32_t& b1, uint32_t a) {
    asm volatile("ldmatrix.sync.aligned.m8n8.x2.trans.shared.b16 {%0,%1},[%2];"
        : "=r"(b0), "=r"(b1) : "r"(a));
}
__device__ __forceinline__ void mma16816(float& d0, float& d1, float& d2, float& d3,
    uint32_t a0, uint32_t a1, uint32_t a2, uint32_t a3, uint32_t b0, uint32_t b1) {
    asm volatile("mma.sync.aligned.m16n8k16.row.col.f32.f16.f16.f32 "
        "{%0,%1,%2,%3},{%4,%5,%6,%7},{%8,%9},{%0,%1,%2,%3};"
        : "+f"(d0), "+f"(d1), "+f"(d2), "+f"(d3)
        : "r"(a0), "r"(a1), "r"(a2), "r"(a3), "r"(b0), "r"(b1));
}

__device__ __forceinline__ void gbar() {
    __syncthreads();
    __threadfence();
    if (threadIdx.x == 0) {
        unsigned my = *(volatile unsigned*)&g_gen;
        unsigned old = atomicAdd(&g_cnt, 1u);
        if (old == NBLK - 1) { g_cnt = 0u; __threadfence(); atomicAdd(&g_gen, 1u); }
        else { while (*(volatile unsigned*)&g_gen == my) { __nanosleep(64); } }
        __threadfence();
    }
    __syncthreads();
}

// ---- launch 1: init state + meta ----
__global__ void setup_a(const float* __restrict__ values, const int* __restrict__ lens) {
    if (blockIdx.x == 0) {
        __shared__ int pre[NB + 1];
        if (threadIdx.x == 0) {
            int s = 0;
            for (int n = 0; n < NB; n++) { pre[n] = s; s += lens[n]; }
            pre[NB] = s;
            for (int i = 0; i <= NB; i++) g_prefix[i] = pre[i];
        }
        __syncthreads();
        int n = threadIdx.x;
        if (n < NB) {
            long long W = pre[NB];
            int Pn = pre[n], Pn1 = pre[n + 1], bf = 0, bl = 0, cnt = 0;
            for (int b = 0; b < NBLK; b++) {
                int r0 = (int)((long long)b * W / NBLK);
                int r1 = (int)((long long)(b + 1) * W / NBLK);
                if (max(r0, Pn) < min(r1, Pn1)) { if (cnt == 0) bf = b; bl = b; cnt++; }
            }
            g_bfirst[n] = bf; g_blast[n] = bl; g_bcnt[n] = cnt;
        }
        return;
    }
    int i = (blockIdx.x - 1) * 256 + threadIdx.x;   // 512 worker blocks
    if (i < 512 * 128) g_c1[i] = 0.0f;
    if (i < 128 * 128) { g_c2[i] = 0.0f; g_x2[1][512 * 128 + i] = __float2half(0.0f); }
    if (i < 640 * 128) {
        int k = i >> 7, n = i & 127;
        g_x1[0][i] = (k < 128) ? __float2half(values[n * 128 + k]) : __float2half(0.0f);
    }
    if (i < NB) g_acnt[i] = 0;
}

// ---- launch 2: K/V transpose to [n][t][f] fp16 ----
__global__ void convkv_kernel(const float* __restrict__ key, const float* __restrict__ val) {
    int rid = blockIdx.x * 8 + (threadIdx.x >> 5);
    int lane = threadIdx.x & 31;
    if (rid < TT * NB) {
        int t = rid >> 7, n = rid & 127;
        float4 kv = *(const float4*)(key + ((size_t)rid << 7) + (lane << 2));
        float4 vv = *(const float4*)(val + ((size_t)rid << 7) + (lane << 2));
        size_t dst = ((size_t)n * TT + t) * 128 + (lane << 2);
        ((__half2*)(g_kb + dst))[0] = __floats2half2_rn(kv.x, kv.y);
        ((__half2*)(g_kb + dst))[1] = __floats2half2_rn(kv.z, kv.w);
        ((__half2*)(g_vb + dst))[0] = __floats2half2_rn(vv.x, vv.y);
        ((__half2*)(g_vb + dst))[1] = __floats2half2_rn(vv.z, vv.w);
    }
}

// ---- launch 3: weight permute/convert + PbT ----
__global__ void setup_b(const float* __restrict__ W_ih1, const float* __restrict__ W_hh1,
                        const float* __restrict__ W_ih2, const float* __restrict__ W_hh2,
                        const float* __restrict__ emb,
                        const float* __restrict__ b_ih1, const float* __restrict__ b_hh1) {
    int idx = blockIdx.x;    // 2624 blocks
    if (idx < 2048) {
        int ct = idx >> 4, r = idx & 15;
        int ca = ((r & 3) << 9) + ct * 4 + (r >> 2);
        for (int k = threadIdx.x; k < 640; k += 256) {
            float v = (k < 128) ? W_ih1[(size_t)ca * 640 + 512 + k]
                                : W_hh1[(size_t)ca * 512 + (k - 128)];
            g_W1p[(size_t)idx * 640 + k] = __float2half(v);
        }
    } else if (idx < 2560) {
        int i2 = idx - 2048, ct = i2 >> 4, r = i2 & 15;
        int cb = ((r & 3) << 7) + ct * 4 + (r >> 2);
        for (int k = threadIdx.x; k < 640; k += 256) {
            float v = (k < 512) ? W_ih2[(size_t)cb * 512 + k]
                                : W_hh2[(size_t)cb * 128 + (k - 512)];
            g_W2p[(size_t)i2 * 640 + k] = __float2half(v);
        }
    } else {
        const int ca = (idx - 2560) * 32 + (threadIdx.x & 31);
        const int rg = threadIdx.x >> 5;
        float acc[8];
#pragma unroll
        for (int i = 0; i < 8; i++) acc[i] = 0.0f;
        for (int k = 0; k < HH; k++) {
            float w = W_ih1[(size_t)ca * 640 + k];
#pragma unroll
            for (int i = 0; i < 8; i++) acc[i] = fmaf(emb[(size_t)(rg * 8 + i) * HH + k], w, acc[i]);
        }
        float bb = b_ih1[ca] + b_hh1[ca];
#pragma unroll
        for (int i = 0; i < 8; i++) g_PbT[(size_t)ca * 64 + rg * 8 + i] = acc[i] + bb;
    }
}

// ---- launch 4: persistent decoder ----
__global__ __launch_bounds__(NTHR, 2) void decoder_main(
    const int* __restrict__ text,
    const float* __restrict__ b_ih2, const float* __restrict__ b_hh2,
    const float* __restrict__ W_mos, const float* __restrict__ b_mos,
    float* __restrict__ out)
{
    extern __shared__ __align__(16) char sm[];
    __half* W1s = (__half*)(sm + OFF_W1);
    __half* W2s = (__half*)(sm + OFF_W2);
    __half* Xs  = (__half*)(sm + OFF_XS);
    float*  sgA = (float*)(sm + OFF_U);
    SCt&    sc  = *(SCt*)(sm + OFF_U);
    __shared__ int toks[64];
    __shared__ int s_pre[NB + 1];

    const int blk = blockIdx.x, tid = threadIdx.x;
    const int w = tid >> 5, lane = tid & 31;
    const uint32_t uW1 = cvta_s(W1s), uW2 = cvta_s(W2s), uXs = cvta_s(Xs);

    {   // persistent weight tiles -> smem
        const int ct = blk >> 1;
        for (int s = tid; s < 1280; s += NTHR) {
            int r = s / 80, seg = s - r * 80;
            *(uint4*)&W1s[r * WST + seg * 8] = *(const uint4*)&g_W1p[(size_t)(ct * 16 + r) * 640 + seg * 8];
        }
        if (blk < 64) {
            const int bt = blk >> 1;
            for (int s = tid; s < 1280; s += NTHR) {
                int r = s / 80, seg = s - r * 80;
                *(uint4*)&W2s[r * WST + seg * 8] = *(const uint4*)&g_W2p[(size_t)(bt * 16 + r) * 640 + seg * 8];
            }
        }
        for (int i = tid; i <= NB; i += NTHR) s_pre[i] = g_prefix[i];
    }
    __syncthreads();

    // loop-invariant attention partition
    const long long Wtot = s_pre[NB];
    const int r0 = (int)((long long)blk * Wtot / NBLK);
    const int r1 = (int)((long long)(blk + 1) * Wtot / NBLK);
    int n0 = 0;
    for (int n = 1; n < NB; n++) { if (s_pre[n] <= r0) n0 = n; else break; }

    // split-K geometry
    const int grp = tid >> 8;                 // warp group 0/1
    const int tg  = tid & 255;
    const int ww  = (tid >> 5) & 7;           // warp within group
    const int sr  = tg >> 2, sseg = tg & 3;
    __half* Xg = Xs + grp * XBUF;
    const uint32_t uXg = uXs + grp * XBUF * 2;
    const uint32_t aOfs = (uint32_t)(lane & 15) * WST + ((lane >> 4) << 3);
    const uint32_t stA = (uint32_t)(sr * XST + sseg * 8);

    for (int l = 0; l < LL; l++) {
        const int q = l & 1;

        // ===== phase A: LSTM1 gates, split-K HMMA =====
        {
            const int ct = blk >> 1, nh = blk & 1;
            if (tid < 64) toks[tid] = text[((nh << 6) + tid) * LL + l];
            const __half* x1p = g_x1[q] + (nh << 6);
            float d0 = 0.f, d1 = 0.f, d2 = 0.f, d3 = 0.f;
            uint4 pf0, pf1;
            {
                const __half* s = x1p + (((grp * 5) * 64 + sr) << 7);
                pf0 = *(const uint4*)(s + sseg * 8);
                pf1 = *(const uint4*)(s + 32 + sseg * 8);
            }
#pragma unroll 1
            for (int i = 0; i < 5; i++) {
                __syncthreads();
                *(uint4*)&Xg[stA]      = pf0;
                *(uint4*)&Xg[stA + 32] = pf1;
                __syncthreads();
                if (i < 4) {
                    const __half* s = x1p + (((grp * 5 + i + 1) * 64 + sr) << 7);
                    pf0 = *(const uint4*)(s + sseg * 8);
                    pf1 = *(const uint4*)(s + 32 + sseg * 8);
                }
                const int ch = grp * 5 + i;
#pragma unroll
                for (int ks = 0; ks < 4; ks++) {
                    uint32_t a0, a1, a2, a3, b0, b1;
                    ldsm_x4(a0, a1, a2, a3, uW1 + (aOfs + (ch << 6) + (ks << 4)) * 2);
                    ldsm_x2t(b0, b1, uXg + ((((ks << 4) + (lane & 15)) * XST) + (ww << 3)) * 2);
                    mma16816(d0, d1, d2, d3, a0, a1, a2, a3, b0, b1);
                }
            }
            __syncthreads();
            {
                int r = lane >> 2, c = (ww << 3) + ((lane & 3) << 1);
                float* dst = sgA + grp * 1088;
                dst[r * 68 + c] = d0;       dst[r * 68 + c + 1] = d1;
                dst[(r + 8) * 68 + c] = d2; dst[(r + 8) * 68 + c + 1] = d3;
            }
            __syncthreads();
            if (tid < 256) {
                const int u = tid >> 6, an = tid & 63, n = (nh << 6) + an;
                const int tok = toks[an];
                const int base = ct * 4 + u;
                float gi = sgA[(4 * u + 0) * 68 + an] + sgA[1088 + (4 * u + 0) * 68 + an] + g_PbT[(size_t)(base) * 64 + tok];
                float gf = sgA[(4 * u + 1) * 68 + an] + sgA[1088 + (4 * u + 1) * 68 + an] + g_PbT[(size_t)(512 + base) * 64 + tok];
                float gg = sgA[(4 * u + 2) * 68 + an] + sgA[1088 + (4 * u + 2) * 68 + an] + g_PbT[(size_t)(1024 + base) * 64 + tok];
                float go = sgA[(4 * u + 3) * 68 + an] + sgA[1088 + (4 * u + 3) * 68 + an] + g_PbT[(size_t)(1536 + base) * 64 + tok];
                const int ci = (base << 7) + n;
                float cn = sigf(gf) * g_c1[ci] + sigf(gi) * tanhf(gg);
                g_c1[ci] = cn;
                __half hval = __float2half(sigf(go) * tanhf(cn));
                g_x1[q ^ 1][((128 + base) << 7) + n] = hval;
                g_x2[q ^ 1][(base << 7) + n] = hval;
            }
        }
        gbar();

        // ===== phase B: LSTM2 gates (64 blocks), split-K HMMA =====
        if (blk < 64) {
            const int bt = blk >> 1, nh = blk & 1;
            const __half* x2p = g_x2[q ^ 1] + (nh << 6);
            float d0 = 0.f, d1 = 0.f, d2 = 0.f, d3 = 0.f;
            uint4 pf0, pf1;
            {
                const __half* s = x2p + (((grp * 5) * 64 + sr) << 7);
                pf0 = *(const uint4*)(s + sseg * 8);
                pf1 = *(const uint4*)(s + 32 + sseg * 8);
            }
#pragma unroll 1
            for (int i = 0; i < 5; i++) {
                __syncthreads();
                *(uint4*)&Xg[stA]      = pf0;
                *(uint4*)&Xg[stA + 32] = pf1;
                __syncthreads();
                if (i < 4) {
                    const __half* s = x2p + (((grp * 5 + i + 1) * 64 + sr) << 7);
                    pf0 = *(const uint4*)(s + sseg * 8);
                    pf1 = *(const uint4*)(s + 32 + sseg * 8);
                }
                const int ch = grp * 5 + i;
#pragma unroll
                for (int ks = 0; ks < 4; ks++) {
                    uint32_t a0, a1, a2, a3, b0, b1;
                    ldsm_x4(a0, a1, a2, a3, uW2 + (aOfs + (ch << 6) + (ks << 4)) * 2);
                    ldsm_x2t(b0, b1, uXg + ((((ks << 4) + (lane & 15)) * XST) + (ww << 3)) * 2);
                    mma16816(d0, d1, d2, d3, a0, a1, a2, a3, b0, b1);
                }
            }
            __syncthreads();
            {
                int r = lane >> 2, c = (ww << 3) + ((lane & 3) << 1);
                float* dst = sgA + grp * 1088;
                dst[r * 68 + c] = d0;       dst[r * 68 + c + 1] = d1;
                dst[(r + 8) * 68 + c] = d2; dst[(r + 8) * 68 + c + 1] = d3;
            }
            __syncthreads();
            if (tid < 256) {
                const int u = tid >> 6, an = tid & 63, n = (nh << 6) + an;
                const int base = bt * 4 + u;
                float gi = sgA[(4 * u + 0) * 68 + an] + sgA[1088 + (4 * u + 0) * 68 + an] + b_ih2[base]       + b_hh2[base];
                float gf = sgA[(4 * u + 1) * 68 + an] + sgA[1088 + (4 * u + 1) * 68 + an] + b_ih2[128 + base] + b_hh2[128 + base];
                float gg = sgA[(4 * u + 2) * 68 + an] + sgA[1088 + (4 * u + 2) * 68 + an] + b_ih2[256 + base] + b_hh2[256 + base];
                float go = sgA[(4 * u + 3) * 68 + an] + sgA[1088 + (4 * u + 3) * 68 + an] + b_ih2[384 + base] + b_hh2[384 + base];
                const int ci = (base << 7) + n;
                float cn = sigf(gf) * g_c2[ci] + sigf(gi) * tanhf(gg);
                g_c2[ci] = cn;
                float h2v = sigf(go) * tanhf(cn);
                g_h2N[(n << 7) + base] = h2v;
                g_x2[q][((512 + base) << 7) + n] = __float2half(h2v);
            }
        }
        gbar();

        // ===== phase C: balanced flash attention (16 warps) + combine + MoS =====
        {
            for (int n = n0; n < NB && s_pre[n] < r1; n++) {
                const int Pn = s_pre[n], Pn1 = s_pre[n + 1];
                const int tlo = max(r0, Pn) - Pn;
                const int thi = min(r1, Pn1) - Pn;
                if (thi <= tlo) continue;

                if (tid < KK) sc.h2s[tid] = __ldcg(&g_h2N[(n << 7) + tid]);
                __syncthreads();
                const float4 hv = *(const float4*)&sc.h2s[lane << 2];

                float m = -1e30f, ssum = 0.0f;
                float4 acc = make_float4(0.f, 0.f, 0.f, 0.f);
                const __half* kbase = g_kb + (size_t)n * TT * 128 + (lane << 2);
                const __half* vbase = g_vb + (size_t)n * TT * 128 + (lane << 2);

                int t = tlo + w;
                for (; t + 16 < thi; t += 32) {
                    const __half* kp = kbase + (size_t)t * 128;
                    const __half* vp = vbase + (size_t)t * 128;
                    uint2 kw0 = *(const uint2*)kp;
                    uint2 kw1 = *(const uint2*)(kp + 2048);
                    uint2 vw0 = *(const uint2*)vp;
                    uint2 vw1 = *(const uint2*)(vp + 2048);
                    float2 a0 = __half22float2(*(__half2*)&kw0.x);
                    float2 b0 = __half22float2(*(__half2*)&kw0.y);
                    float2 a1 = __half22float2(*(__half2*)&kw1.x);
                    float2 b1 = __half22float2(*(__half2*)&kw1.y);
                    float d0 = a0.x * hv.x + a0.y * hv.y + b0.x * hv.z + b0.y * hv.w;
                    float d1 = a1.x * hv.x + a1.y * hv.y + b1.x * hv.z + b1.y * hv.w;
#pragma unroll
                    for (int o = 16; o; o >>= 1) {
                        d0 += __shfl_xor_sync(0xffffffffu, d0, o);
                        d1 += __shfl_xor_sync(0xffffffffu, d1, o);
                    }
                    float mn = fmaxf(m, fmaxf(d0, d1));
                    float scale = __expf(m - mn);
                    float p0 = __expf(d0 - mn), p1 = __expf(d1 - mn);
                    ssum = ssum * scale + (p0 + p1);
                    float2 va0 = __half22float2(*(__half2*)&vw0.x);
                    float2 vb0 = __half22float2(*(__half2*)&vw0.y);
                    float2 va1 = __half22float2(*(__half2*)&vw1.x);
                    float2 vb1 = __half22float2(*(__half2*)&vw1.y);
                    acc.x = acc.x * scale + p0 * va0.x + p1 * va1.x;
                    acc.y = acc.y * scale + p0 * va0.y + p1 * va1.y;
                    acc.z = acc.z * scale + p0 * vb0.x + p1 * vb1.x;
                    acc.w = acc.w * scale + p0 * vb0.y + p1 * vb1.y;
                    m = mn;
                }
                for (; t < thi; t += 16) {
                    const __half* kp = kbase + (size_t)t * 128;
                    const __half* vp = vbase + (size_t)t * 128;
                    uint2 kw = *(const uint2*)kp;
                    uint2 vw = *(const uint2*)vp;
                    float2 a0 = __half22float2(*(__half2*)&kw.x);
                    float2 b0 = __half22float2(*(__half2*)&kw.y);
                    float d = a0.x * hv.x + a0.y * hv.y + b0.x * hv.z + b0.y * hv.w;
#pragma unroll
                    for (int o = 16; o; o >>= 1) d += __shfl_xor_sync(0xffffffffu, d, o);
                    float mn = fmaxf(m, d);
                    float scale = __expf(m - mn);
                    float pp = __expf(d - mn);
                    ssum = ssum * scale + pp;
                    float2 va = __half22float2(*(__half2*)&vw.x);
                    float2 vb = __half22float2(*(__half2*)&vw.y);
                    acc.x = acc.x * scale + pp * va.x;
                    acc.y = acc.y * scale + pp * va.y;
                    acc.z = acc.z * scale + pp * vb.x;
                    acc.w = acc.w * scale + pp * vb.y;
                    m = mn;
                }

                if (lane == 0) { sc.wm[w] = m; sc.wsum[w] = ssum; }
                *(float4*)&sc.wacc[w][lane << 2] = acc;
                __syncthreads();

                const int slot = blk - g_bfirst[n];
                if (tid < VV) {
                    float mm = -1e30f;
#pragma unroll
                    for (int ww2 = 0; ww2 < 16; ww2++) mm = fmaxf(mm, sc.wm[ww2]);
                    float S = 0.0f, C = 0.0f;
#pragma unroll
                    for (int ww2 = 0; ww2 < 16; ww2++) {
                        float e = __expf(sc.wm[ww2] - mm);
                        S += e * sc.wsum[ww2];
                        C += e * sc.wacc[ww2][tid];
                    }
                    g_pacc[((size_t)n * NBLK + slot) * VV + tid] = C;
                    if (tid == 0) { g_pm[n * NBLK + slot] = mm; g_ps[n * NBLK + slot] = S; }
                    __threadfence();
                }
                __syncthreads();
                if (tid == 0) {
                    int old = atomicAdd(&g_acnt[n], 1);
                    __threadfence();
                    sc.flag = (old == g_bcnt[n] - 1);
                }
                __syncthreads();
                if (sc.flag) {
                    const int bf = g_bfirst[n], bl = g_blast[n];
                    if (tid < VV) {
                        float mm = -1e30f;
                        for (int bb = bf; bb <= bl; bb++) {
                            int rr0 = (int)((long long)bb * Wtot / NBLK);
                            int rr1 = (int)((long long)(bb + 1) * Wtot / NBLK);
                            if (max(rr0, Pn) < min(rr1, Pn1))
                                mm = fmaxf(mm, __ldcg(&g_pm[n * NBLK + (bb - bf)]));
                        }
                        float S = 0.0f, C = 0.0f;
                        for (int bb = bf; bb <= bl; bb++) {
                            int rr0 = (int)((long long)bb * Wtot / NBLK);
                            int rr1 = (int)((long long)(bb + 1) * Wtot / NBLK);
                            if (max(rr0, Pn) < min(rr1, Pn1)) {
                                int s2 = bb - bf;
                                float e = __expf(__ldcg(&g_pm[n * NBLK + s2]) - mm);
                                S += e * __ldcg(&g_ps[n * NBLK + s2]);
                                C += e * __ldcg(&g_pacc[((size_t)n * NBLK + s2) * VV + tid]);
                            }
                        }
                        float cv = C / S;
                        sc.ctxs[tid] = cv;
                        g_x1[q ^ 1][(tid << 7) + n] = __float2half(cv);
                    }
                    if (tid == 0) g_acnt[n] = 0;
                    __syncthreads();
                    if (tid < AA) {
                        float a = b_mos[tid];
                        const float* wr = W_mos + (size_t)tid * (KK + VV);
#pragma unroll 4
                        for (int k = 0; k < KK; k++) a = fmaf(sc.h2s[k], wr[k], a);
#pragma unroll 4
                        for (int v = 0; v < VV; v++) a = fmaf(sc.ctxs[v], wr[KK + v], a);
                        out[((size_t)n * LL + l) * AA + tid] = a;
                    }
                }
                __syncthreads();
            }
        }
        gbar();
    }
}

extern "C" void kernel_launch(void* const* d_in, const int* in_sizes, int n_in,
                              void* d_out, int out_size) {
    (void)in_sizes; (void)n_in; (void)out_size;
    const float* key    = (const float*)d_in[0];
    const float* values = (const float*)d_in[1];
    const int*   lens   = (const int*)  d_in[2];
    const int*   text   = (const int*)  d_in[3];
    const float* emb    = (const float*)d_in[4];
    const float* W_ih1  = (const float*)d_in[5];
    const float* W_hh1  = (const float*)d_in[6];
    const float* b_ih1  = (const float*)d_in[7];
    const float* b_hh1  = (const float*)d_in[8];
    const float* W_ih2  = (const float*)d_in[9];
    const float* W_hh2  = (const float*)d_in[10];
    const float* b_ih2  = (const float*)d_in[11];
    const float* b_hh2  = (const float*)d_in[12];
    const float* W_mos  = (const float*)d_in[13];
    const float* b_mos  = (const float*)d_in[14];
    float* out = (float*)d_out;

    static int s_attr = 0;
    if (!s_attr) {
        cudaFuncSetAttribute(decoder_main, cudaFuncAttributeMaxDynamicSharedMemorySize, SMEM_TOTAL);
        s_attr = 1;
    }
    setup_a<<<513, 256>>>(values, lens);
    convkv_kernel<<<32000, 256>>>(key, values);
    setup_b<<<2624, 256>>>(W_ih1, W_hh1, W_ih2, W_hh2, emb, b_ih1, b_hh1);
    decoder_main<<<NBLK, NTHR, SMEM_TOTAL>>>(text, b_ih2, b_hh2, W_mos, b_mos, out);
}